// round 1
// baseline (speedup 1.0000x reference)
#include <cuda_runtime.h>
#include <math.h>

// ---------------------------------------------------------------------------
// Problem constants
// ---------------------------------------------------------------------------
constexpr int N_   = 50000;
constexpr int IN_  = 128;
constexpr int HID_ = 64;
constexpr int H_   = 4;
constexpr int D_   = 64;
constexpr int F_   = 256;    // H*D
constexpr int OUT_ = 16;
constexpr int SAH_ = 128;
constexpr int EMAX_ = 800000;

constexpr int SA_NODES = 8;
constexpr int WS_SMEM = (F_ * SAH_ + SA_NODES * F_) * 4;  // 139264 bytes

// ---------------------------------------------------------------------------
// Device scratch (static allocation — no cudaMalloc allowed)
// ---------------------------------------------------------------------------
__device__ float g_x[(size_t)N_ * HID_];
__device__ float g_z[(size_t)N_ * F_];
__device__ float g_el[N_ * H_];
__device__ float g_er[N_ * H_];
__device__ float g_emax[N_ * H_];
__device__ float g_denom[N_ * H_];
__device__ float g_e[(size_t)EMAX_ * H_];
__device__ float g_emb[3 * (size_t)N_ * F_];
__device__ float g_hl[2 * (size_t)N_ * F_];
__device__ float g_hfin[(size_t)N_ * F_];
__device__ float g_wsum[4];
__device__ float g_beta[4];

// ---------------------------------------------------------------------------
// Helpers
// ---------------------------------------------------------------------------
__device__ __forceinline__ void atomicMaxF(float* a, float v) {
    if (v >= 0.f) atomicMax((int*)a, __float_as_int(v));
    else          atomicMin((unsigned int*)a, __float_as_uint(v));
}

__device__ __forceinline__ void red_add_v4(float* p, float a, float b, float c, float d) {
    asm volatile("red.global.add.v4.f32 [%0], {%1,%2,%3,%4};"
                 :: "l"(p), "f"(a), "f"(b), "f"(c), "f"(d) : "memory");
}

// ---------------------------------------------------------------------------
// x = h @ fc_W   [N,128] @ [128,64]
// ---------------------------------------------------------------------------
__global__ void k_fc(const float* __restrict__ h, const float* __restrict__ W) {
    __shared__ __align__(16) float sW[IN_ * HID_];   // 32 KB
    __shared__ __align__(16) float sh[16 * IN_];     // 8 KB
    int tid = threadIdx.x;
    for (int i = tid; i < IN_ * HID_; i += 256) sW[i] = W[i];
    int row0 = blockIdx.x * 16;
    for (int i = tid; i < 16 * IN_; i += 256) {
        int r = i >> 7, k = i & 127;
        sh[i] = (row0 + r < N_) ? h[(size_t)(row0 + r) * IN_ + k] : 0.f;
    }
    __syncthreads();
    int col = tid & 63;
    for (int rr = tid >> 6; rr < 16; rr += 4) {
        float acc = 0.f;
#pragma unroll
        for (int k = 0; k < IN_; k += 4) {
            float4 hv = *(const float4*)&sh[rr * IN_ + k];
            acc += hv.x * sW[k * HID_ + col] + hv.y * sW[(k + 1) * HID_ + col]
                 + hv.z * sW[(k + 2) * HID_ + col] + hv.w * sW[(k + 3) * HID_ + col];
        }
        if (row0 + rr < N_) g_x[(size_t)(row0 + rr) * HID_ + col] = acc;
    }
}

// ---------------------------------------------------------------------------
// z = x @ W_m   [N,64] @ [64,256]  (W column cached in registers per thread)
// ---------------------------------------------------------------------------
__global__ void k_z(const float* __restrict__ W) {
    int c = threadIdx.x;  // 0..255
    float wreg[HID_];
#pragma unroll
    for (int k = 0; k < HID_; k++) wreg[k] = W[k * F_ + c];
    __shared__ __align__(16) float sx[64 * HID_];  // 16 KB
    int row0 = blockIdx.x * 64;
    for (int i = threadIdx.x; i < 64 * HID_; i += 256) {
        int r = i >> 6, k = i & 63;
        sx[i] = (row0 + r < N_) ? g_x[(size_t)(row0 + r) * HID_ + k] : 0.f;
    }
    __syncthreads();
    int rmax = min(64, N_ - row0);
    for (int r = 0; r < rmax; r++) {
        float acc = 0.f;
#pragma unroll
        for (int k = 0; k < HID_; k += 4) {
            float4 xv = *(const float4*)&sx[r * HID_ + k];
            acc += xv.x * wreg[k] + xv.y * wreg[k + 1] + xv.z * wreg[k + 2] + xv.w * wreg[k + 3];
        }
        g_z[(size_t)(row0 + r) * F_ + c] = acc;
    }
}

// ---------------------------------------------------------------------------
// el[n,h] = sum_d z*al,  er[n,h] = sum_d z*ar
// ---------------------------------------------------------------------------
__global__ void k_eler(const float* __restrict__ al, const float* __restrict__ ar) {
    int n = blockIdx.x;
    int h = threadIdx.x >> 5, lane = threadIdx.x & 31;
    const float* zr = g_z + (size_t)n * F_ + h * D_;
    const float* alr = al + h * D_;
    const float* arr = ar + h * D_;
    float a = zr[lane] * alr[lane] + zr[lane + 32] * alr[lane + 32];
    float b = zr[lane] * arr[lane] + zr[lane + 32] * arr[lane + 32];
#pragma unroll
    for (int o = 16; o > 0; o >>= 1) {
        a += __shfl_down_sync(0xffffffffu, a, o);
        b += __shfl_down_sync(0xffffffffu, b, o);
    }
    if (lane == 0) { g_el[n * H_ + h] = a; g_er[n * H_ + h] = b; }
}

// ---------------------------------------------------------------------------
// Per-conv init: zero accumulator slot, emax=-inf, denom=0
// ---------------------------------------------------------------------------
__global__ void k_init(int m) {
    int i = blockIdx.x * 256 + threadIdx.x;
    if (i < N_ * F_) g_emb[(size_t)m * N_ * F_ + i] = 0.f;
    if (i < N_ * H_) { g_emax[i] = __int_as_float(0xff800000); g_denom[i] = 0.f; }
}

// ---------------------------------------------------------------------------
// Edge pass A: e = leaky_relu(el[src]+er[dst]); segment max by dst
// ---------------------------------------------------------------------------
__global__ void k_edgeA(const int* __restrict__ src, const int* __restrict__ dst, int E) {
    int i = blockIdx.x * 256 + threadIdx.x;
    if (i >= E * H_) return;
    int e = i >> 2, hh = i & 3;
    int s = src[e], d = dst[e];
    float v = g_el[s * H_ + hh] + g_er[d * H_ + hh];
    v = v > 0.f ? v : 0.2f * v;
    g_e[i] = v;
    atomicMaxF(&g_emax[d * H_ + hh], v);
}

// ---------------------------------------------------------------------------
// Edge pass B: ex = exp(e - emax[dst]); segment sum by dst
// ---------------------------------------------------------------------------
__global__ void k_edgeB(const int* __restrict__ dst, int E) {
    int i = blockIdx.x * 256 + threadIdx.x;
    if (i >= E * H_) return;
    int e = i >> 2, hh = i & 3;
    int d = dst[e];
    float ex = __expf(g_e[i] - g_emax[d * H_ + hh]);
    g_e[i] = ex;
    atomicAdd(&g_denom[d * H_ + hh], ex);
}

// ---------------------------------------------------------------------------
// Edge pass C: emb[m][dst] += (ex/denom[dst]) * z[src]  — warp per edge
// ---------------------------------------------------------------------------
__global__ void k_edgeC(const int* __restrict__ src, const int* __restrict__ dst, int E, int m) {
    int gw = (blockIdx.x * blockDim.x + threadIdx.x) >> 5;
    if (gw >= E) return;
    int lane = threadIdx.x & 31;
    int s = src[gw], d = dst[gw];
    int j0 = lane * 8;
    int hh = lane >> 3;
    float alpha = g_e[gw * H_ + hh] / g_denom[d * H_ + hh];
    const float4* zp = (const float4*)(g_z + (size_t)s * F_ + j0);
    float4 v0 = zp[0], v1 = zp[1];
    float* op = g_emb + (size_t)m * N_ * F_ + (size_t)d * F_ + j0;
    red_add_v4(op,     v0.x * alpha, v0.y * alpha, v0.z * alpha, v0.w * alpha);
    red_add_v4(op + 4, v1.x * alpha, v1.y * alpha, v1.z * alpha, v1.w * alpha);
}

// ---------------------------------------------------------------------------
// out = elu(acc + b)
// ---------------------------------------------------------------------------
__global__ void k_biaselu(const float* __restrict__ b, int m) {
    int i = blockIdx.x * 256 + threadIdx.x;
    if (i >= N_ * F_) return;
    float v = g_emb[(size_t)m * N_ * F_ + i] + b[i & (F_ - 1)];
    g_emb[(size_t)m * N_ * F_ + i] = v > 0.f ? v : expm1f(v);
}

// ---------------------------------------------------------------------------
// Semantic attention score accumulation:
// wsum[m] += sum_n  w2 . tanh(z[n,m,:] @ W1 + b1)
// Block: 128 threads (one per k), 8 nodes register-batched, W1 in smem.
// ---------------------------------------------------------------------------
__global__ void k_zerow() { if (threadIdx.x < 4) g_wsum[threadIdx.x] = 0.f; }

__global__ void k_wscore(int base_sel, int M,
                         const float* __restrict__ W1,
                         const float* __restrict__ b1,
                         const float* __restrict__ w2) {
    extern __shared__ __align__(16) float smem[];
    float* sW1 = smem;                  // F_*SAH_ floats (128 KB)
    float* sz  = smem + F_ * SAH_;      // SA_NODES*F_ floats (8 KB)
    int tid = threadIdx.x;              // 0..127 == k
    for (int i = tid; i < F_ * SAH_; i += 128) sW1[i] = W1[i];
    float b1k = b1[tid], w2k = w2[tid];
    const float* base = (base_sel == 0) ? g_emb : g_hl;
    int node0 = blockIdx.x * SA_NODES;
    float accm[3] = {0.f, 0.f, 0.f};
    for (int m = 0; m < M; m++) {
        const float* Z = base + (size_t)m * N_ * F_;
        __syncthreads();
        for (int i = tid; i < SA_NODES * F_; i += 128) {
            int r = i >> 8, f = i & 255;
            sz[i] = (node0 + r < N_) ? Z[(size_t)(node0 + r) * F_ + f] : 0.f;
        }
        __syncthreads();
        float a[SA_NODES];
#pragma unroll
        for (int j = 0; j < SA_NODES; j++) a[j] = b1k;
        for (int f = 0; f < F_; f += 4) {
            float w0 = sW1[f * SAH_ + tid];
            float w1 = sW1[(f + 1) * SAH_ + tid];
            float w2v = sW1[(f + 2) * SAH_ + tid];
            float w3 = sW1[(f + 3) * SAH_ + tid];
#pragma unroll
            for (int j = 0; j < SA_NODES; j++) {
                float4 zv = *(const float4*)&sz[j * F_ + f];
                a[j] += zv.x * w0 + zv.y * w1 + zv.z * w2v + zv.w * w3;
            }
        }
#pragma unroll
        for (int j = 0; j < SA_NODES; j++)
            if (node0 + j < N_) accm[m] += tanhf(a[j]) * w2k;
    }
    // block reduce each accm[m] and atomically accumulate
    __shared__ float sred[4];
    int lane = tid & 31, warp = tid >> 5;
    for (int m = 0; m < M; m++) {
        float v = accm[m];
#pragma unroll
        for (int o = 16; o > 0; o >>= 1) v += __shfl_down_sync(0xffffffffu, v, o);
        if (lane == 0) sred[warp] = v;
        __syncthreads();
        if (tid == 0) atomicAdd(&g_wsum[m], sred[0] + sred[1] + sred[2] + sred[3]);
        __syncthreads();
    }
}

__global__ void k_beta(int M) {
    if (threadIdx.x == 0) {
        float w[3];
        float mx = -1e30f;
        for (int m = 0; m < M; m++) { w[m] = g_wsum[m] / (float)N_; mx = fmaxf(mx, w[m]); }
        float s = 0.f;
        for (int m = 0; m < M; m++) { w[m] = __expf(w[m] - mx); s += w[m]; }
        for (int m = 0; m < M; m++) g_beta[m] = w[m] / s;
    }
}

// out_sel: 0 -> g_hl slot0, 1 -> g_hl slot1, 2 -> g_hfin
__global__ void k_combine(int base_sel, int M, int out_sel) {
    int i = blockIdx.x * 256 + threadIdx.x;
    if (i >= N_ * F_) return;
    const float* base = (base_sel == 0) ? g_emb : g_hl;
    float acc = 0.f;
    for (int m = 0; m < M; m++) acc += g_beta[m] * base[(size_t)m * N_ * F_ + i];
    float* out = (out_sel == 0) ? g_hl : (out_sel == 1 ? g_hl + (size_t)N_ * F_ : g_hfin);
    out[i] = acc;
}

// ---------------------------------------------------------------------------
// logits = h_final @ pred_W + pred_b
// ---------------------------------------------------------------------------
__global__ void k_pred(const float* __restrict__ W, const float* __restrict__ b,
                       float* __restrict__ out) {
    __shared__ float sW[F_ * OUT_];  // 16 KB
    int tid = threadIdx.x;
    for (int i = tid; i < F_ * OUT_; i += 256) sW[i] = W[i];
    __syncthreads();
    int node = blockIdx.x * 16 + (tid >> 4);
    int o = tid & 15;
    if (node >= N_) return;
    const float* hr = g_hfin + (size_t)node * F_;
    float acc = b[o];
#pragma unroll 8
    for (int f = 0; f < F_; f++) acc += hr[f] * sW[f * OUT_ + o];
    out[(size_t)node * OUT_ + o] = acc;
}

__global__ void k_copy(float* __restrict__ out) {
    int i = blockIdx.x * 256 + threadIdx.x;
    if (i < N_ * F_) out[i] = g_hfin[i];
}

// ---------------------------------------------------------------------------
// Host launcher — graph-capturable (kernel launches only)
// ---------------------------------------------------------------------------
extern "C" void kernel_launch(void* const* d_in, const int* in_sizes, int n_in,
                              void* d_out, int out_size) {
    const float* h = (const float*)d_in[0];
    const int* srcs[4] = {(const int*)d_in[1], (const int*)d_in[3], (const int*)d_in[5], (const int*)d_in[7]};
    const int* dsts[4] = {(const int*)d_in[2], (const int*)d_in[4], (const int*)d_in[6], (const int*)d_in[8]};
    int Eg[4] = {in_sizes[1], in_sizes[3], in_sizes[5], in_sizes[7]};
    const float* fcW = (const float*)d_in[10];
    const float* W[2]    = {(const float*)d_in[11], (const float*)d_in[18]};
    const float* al[2]   = {(const float*)d_in[12], (const float*)d_in[19]};
    const float* ar[2]   = {(const float*)d_in[13], (const float*)d_in[20]};
    const float* bb[2]   = {(const float*)d_in[14], (const float*)d_in[21]};
    const float* saW1[2] = {(const float*)d_in[15], (const float*)d_in[22]};
    const float* sab1[2] = {(const float*)d_in[16], (const float*)d_in[23]};
    const float* saw2[2] = {(const float*)d_in[17], (const float*)d_in[24]};
    const float* saW1f = (const float*)d_in[25];
    const float* sab1f = (const float*)d_in[26];
    const float* saw2f = (const float*)d_in[27];
    const float* predW = (const float*)d_in[28];
    const float* predb = (const float*)d_in[29];
    float* out = (float*)d_out;

    cudaFuncSetAttribute(k_wscore, cudaFuncAttributeMaxDynamicSharedMemorySize, WS_SMEM);

    k_fc<<<(N_ + 15) / 16, 256>>>(h, fcW);

    const int graphsel[2][3] = {{0, 1, 2}, {0, 1, 3}};
    for (int L = 0; L < 2; L++) {
        for (int m = 0; m < 3; m++) {
            int g = graphsel[L][m];
            int E = Eg[g];
            k_z<<<(N_ + 63) / 64, 256>>>(W[L] + (size_t)m * HID_ * F_);
            k_eler<<<N_, 128>>>(al[L] + m * F_, ar[L] + m * F_);
            k_init<<<(N_ * F_ + 255) / 256, 256>>>(m);
            k_edgeA<<<(E * H_ + 255) / 256, 256>>>(srcs[g], dsts[g], E);
            k_edgeB<<<(E * H_ + 255) / 256, 256>>>(dsts[g], E);
            k_edgeC<<<(E + 7) / 8, 256>>>(srcs[g], dsts[g], E, m);
            k_biaselu<<<(N_ * F_ + 255) / 256, 256>>>(bb[L] + m * F_, m);
        }
        k_zerow<<<1, 32>>>();
        k_wscore<<<(N_ + SA_NODES - 1) / SA_NODES, 128, WS_SMEM>>>(0, 3, saW1[L], sab1[L], saw2[L]);
        k_beta<<<1, 32>>>(3);
        k_combine<<<(N_ * F_ + 255) / 256, 256>>>(0, 3, L);
    }

    k_zerow<<<1, 32>>>();
    k_wscore<<<(N_ + SA_NODES - 1) / SA_NODES, 128, WS_SMEM>>>(1, 2, saW1f, sab1f, saw2f);
    k_beta<<<1, 32>>>(2);
    k_combine<<<(N_ * F_ + 255) / 256, 256>>>(1, 2, 2);

    k_pred<<<(N_ + 15) / 16, 256>>>(predW, predb, out);
    if (out_size >= N_ * (OUT_ + F_))
        k_copy<<<(N_ * F_ + 255) / 256, 256>>>(out + (size_t)N_ * OUT_);
}

// round 2
// speedup vs baseline: 1.3786x; 1.3786x over previous
#include <cuda_runtime.h>
#include <math.h>
#include <float.h>

// ---------------------------------------------------------------------------
// Problem constants
// ---------------------------------------------------------------------------
constexpr int N_   = 50000;
constexpr int IN_  = 128;
constexpr int HID_ = 64;
constexpr int H_   = 4;
constexpr int F_   = 256;    // H*D
constexpr int OUT_ = 16;
constexpr int SAH_ = 128;
constexpr int EMAX_ = 800000;

constexpr int SAN = 8;                       // nodes per wscore block
constexpr size_t NF = (size_t)N_ * F_;
constexpr int CHUNK = 128;                   // conv alpha chunk

// ---------------------------------------------------------------------------
// Device scratch (static — no cudaMalloc allowed)
// ---------------------------------------------------------------------------
__device__ float g_x[(size_t)N_ * HID_];
__device__ float g_z[NF];
__device__ __align__(16) float g_el[N_ * H_];
__device__ __align__(16) float g_er[N_ * H_];
__device__ float g_emb[3 * NF];
__device__ float g_hl[2 * NF];
__device__ float g_hfin[NF];
__device__ float g_wsum[4];
__device__ float g_beta[4];

// CSR scratch
__device__ int g_rowptr[4][N_ + 1];
__device__ int g_esrc[4][EMAX_];
__device__ int g_cnt[N_];
__device__ int g_cursor[N_];

// ---------------------------------------------------------------------------
// f32x2 packed-FMA helpers (Blackwell FFMA2 — only reachable via PTX)
// ---------------------------------------------------------------------------
__device__ __forceinline__ void fma2(unsigned long long& acc,
                                     unsigned long long a, unsigned long long b) {
    asm("fma.rn.f32x2 %0, %1, %2, %0;" : "+l"(acc) : "l"(a), "l"(b));
}
__device__ __forceinline__ unsigned long long packf2(float lo, float hi) {
    unsigned long long r;
    asm("mov.b64 %0, {%1,%2};" : "=l"(r) : "f"(lo), "f"(hi));
    return r;
}
__device__ __forceinline__ float unpack_sum(unsigned long long p) {
    float lo, hi;
    asm("mov.b64 {%0,%1}, %2;" : "=f"(lo), "=f"(hi) : "l"(p));
    return lo + hi;
}

// ---------------------------------------------------------------------------
// x = h @ fc_W   [N,128] @ [128,64]
// ---------------------------------------------------------------------------
__global__ void k_fc(const float* __restrict__ h, const float* __restrict__ W) {
    __shared__ __align__(16) float sW[IN_ * HID_];
    __shared__ __align__(16) float sh[16 * IN_];
    int tid = threadIdx.x;
    for (int i = tid; i < IN_ * HID_; i += 256) sW[i] = W[i];
    int row0 = blockIdx.x * 16;
    for (int i = tid; i < 16 * IN_; i += 256) {
        int r = i >> 7, k = i & 127;
        sh[i] = (row0 + r < N_) ? h[(size_t)(row0 + r) * IN_ + k] : 0.f;
    }
    __syncthreads();
    int col = tid & 63;
    for (int rr = tid >> 6; rr < 16; rr += 4) {
        float acc = 0.f;
#pragma unroll
        for (int k = 0; k < IN_; k += 4) {
            float4 hv = *(const float4*)&sh[rr * IN_ + k];
            acc += hv.x * sW[k * HID_ + col] + hv.y * sW[(k + 1) * HID_ + col]
                 + hv.z * sW[(k + 2) * HID_ + col] + hv.w * sW[(k + 3) * HID_ + col];
        }
        if (row0 + rr < N_) g_x[(size_t)(row0 + rr) * HID_ + col] = acc;
    }
}

// ---------------------------------------------------------------------------
// z = x @ W_m   [N,64] @ [64,256]
// ---------------------------------------------------------------------------
__global__ void k_z(const float* __restrict__ W) {
    int c = threadIdx.x;
    float wreg[HID_];
#pragma unroll
    for (int k = 0; k < HID_; k++) wreg[k] = W[k * F_ + c];
    __shared__ __align__(16) float sx[64 * HID_];
    int row0 = blockIdx.x * 64;
    for (int i = threadIdx.x; i < 64 * HID_; i += 256) {
        int r = i >> 6, k = i & 63;
        sx[i] = (row0 + r < N_) ? g_x[(size_t)(row0 + r) * HID_ + k] : 0.f;
    }
    __syncthreads();
    int rmax = min(64, N_ - row0);
    for (int r = 0; r < rmax; r++) {
        float acc = 0.f;
#pragma unroll
        for (int k = 0; k < HID_; k += 4) {
            float4 xv = *(const float4*)&sx[r * HID_ + k];
            acc += xv.x * wreg[k] + xv.y * wreg[k + 1] + xv.z * wreg[k + 2] + xv.w * wreg[k + 3];
        }
        g_z[(size_t)(row0 + r) * F_ + c] = acc;
    }
}

// ---------------------------------------------------------------------------
// el/er per node/head
// ---------------------------------------------------------------------------
__global__ void k_eler(const float* __restrict__ al, const float* __restrict__ ar) {
    int n = blockIdx.x;
    int h = threadIdx.x >> 5, lane = threadIdx.x & 31;
    const float* zr = g_z + (size_t)n * F_ + h * 64;
    const float* alr = al + h * 64;
    const float* arr = ar + h * 64;
    float a = zr[lane] * alr[lane] + zr[lane + 32] * alr[lane + 32];
    float b = zr[lane] * arr[lane] + zr[lane + 32] * arr[lane + 32];
#pragma unroll
    for (int o = 16; o > 0; o >>= 1) {
        a += __shfl_down_sync(0xffffffffu, a, o);
        b += __shfl_down_sync(0xffffffffu, b, o);
    }
    if (lane == 0) { g_el[n * H_ + h] = a; g_er[n * H_ + h] = b; }
}

// ---------------------------------------------------------------------------
// CSR construction: zero counts -> histogram -> scan -> scatter
// ---------------------------------------------------------------------------
__global__ void k_zerocnt() {
    int i = blockIdx.x * 256 + threadIdx.x;
    if (i < N_) g_cnt[i] = 0;
}
__global__ void k_hist(const int* __restrict__ dst, int E) {
    int i = blockIdx.x * 256 + threadIdx.x;
    if (i < E) atomicAdd(&g_cnt[dst[i]], 1);
}
__global__ void k_scan(int g) {
    __shared__ int ssum[1024];
    int tid = threadIdx.x;
    const int C = (N_ + 1023) / 1024;  // 49
    int lo = tid * C, hi = min(lo + C, N_);
    if (lo > N_) lo = N_;
    int s = 0;
    for (int i = lo; i < hi; i++) s += g_cnt[i];
    ssum[tid] = s;
    __syncthreads();
    for (int off = 1; off < 1024; off <<= 1) {
        int v = (tid >= off) ? ssum[tid - off] : 0;
        __syncthreads();
        ssum[tid] += v;
        __syncthreads();
    }
    int run = (tid == 0) ? 0 : ssum[tid - 1];
    for (int i = lo; i < hi; i++) {
        int c = g_cnt[i];
        g_rowptr[g][i] = run;
        g_cursor[i] = run;
        run += c;
    }
    if (tid == 1023) g_rowptr[g][N_] = run;
}
__global__ void k_scatter(const int* __restrict__ src, const int* __restrict__ dst,
                          int E, int g) {
    int i = blockIdx.x * 256 + threadIdx.x;
    if (i >= E) return;
    int d = dst[i];
    int pos = atomicAdd(&g_cursor[d], 1);
    g_esrc[g][pos] = src[i];
}

// ---------------------------------------------------------------------------
// Fused GAT conv: per-node online softmax + gather-accumulate + bias + ELU.
// 256 threads per block = one dst node; thread t owns feature f=t, head t>>6.
// ---------------------------------------------------------------------------
__global__ void __launch_bounds__(256) k_conv(int g, const float* __restrict__ b, int m) {
    int n = blockIdx.x;
    int tid = threadIdx.x;
    int e0 = g_rowptr[g][n], e1 = g_rowptr[g][n + 1];
    int deg = e1 - e0;
    const int* esrc = g_esrc[g];

    __shared__ float s_m[8][4];
    __shared__ float s_s[8][4];
    __shared__ float s_Max[4];
    __shared__ float s_Inv[4];
    __shared__ __align__(16) float s_alpha[CHUNK * 4];
    __shared__ int s_src[CHUNK];

    float4 ern = *(const float4*)(g_er + n * 4);

    // ---- phase 1: online max/sum per head over in-edges ----
    float mx[4] = {-FLT_MAX, -FLT_MAX, -FLT_MAX, -FLT_MAX};
    float sm[4] = {0.f, 0.f, 0.f, 0.f};
    for (int e = e0 + tid; e < e1; e += 256) {
        int s = esrc[e];
        float4 els = *(const float4*)(g_el + s * 4);
        float v[4];
        v[0] = els.x + ern.x; v[1] = els.y + ern.y;
        v[2] = els.z + ern.z; v[3] = els.w + ern.w;
#pragma unroll
        for (int h = 0; h < 4; h++) {
            float vv = v[h] > 0.f ? v[h] : 0.2f * v[h];
            float nm = fmaxf(mx[h], vv);
            sm[h] = sm[h] * __expf(mx[h] - nm) + __expf(vv - nm);
            mx[h] = nm;
        }
    }
#pragma unroll
    for (int h = 0; h < 4; h++) {
#pragma unroll
        for (int o = 16; o > 0; o >>= 1) {
            float om = __shfl_xor_sync(0xffffffffu, mx[h], o);
            float os = __shfl_xor_sync(0xffffffffu, sm[h], o);
            float nm = fmaxf(mx[h], om);
            sm[h] = sm[h] * __expf(mx[h] - nm) + os * __expf(om - nm);
            mx[h] = nm;
        }
    }
    int lane = tid & 31, warp = tid >> 5;
    if (lane == 0) {
#pragma unroll
        for (int h = 0; h < 4; h++) { s_m[warp][h] = mx[h]; s_s[warp][h] = sm[h]; }
    }
    __syncthreads();
    if (tid < 4) {
        float M = -FLT_MAX, S = 0.f;
#pragma unroll
        for (int w = 0; w < 8; w++) {
            float om = s_m[w][tid], os = s_s[w][tid];
            float nm = fmaxf(M, om);
            S = S * __expf(M - nm) + os * __expf(om - nm);
            M = nm;
        }
        s_Max[tid] = M;
        s_Inv[tid] = (S > 0.f) ? 1.f / S : 0.f;
    }
    __syncthreads();

    // ---- phase 2: chunked alpha + gather-accumulate ----
    int h = tid >> 6;
    float acc = 0.f;
    for (int base = 0; base < deg; base += CHUNK) {
        int cnt = min(CHUNK, deg - base);
        __syncthreads();
        for (int i = tid; i < cnt; i += 256) {
            int s = esrc[e0 + base + i];
            s_src[i] = s;
            float4 els = *(const float4*)(g_el + s * 4);
            float v0 = els.x + ern.x; v0 = v0 > 0.f ? v0 : 0.2f * v0;
            float v1 = els.y + ern.y; v1 = v1 > 0.f ? v1 : 0.2f * v1;
            float v2 = els.z + ern.z; v2 = v2 > 0.f ? v2 : 0.2f * v2;
            float v3 = els.w + ern.w; v3 = v3 > 0.f ? v3 : 0.2f * v3;
            s_alpha[i * 4 + 0] = __expf(v0 - s_Max[0]) * s_Inv[0];
            s_alpha[i * 4 + 1] = __expf(v1 - s_Max[1]) * s_Inv[1];
            s_alpha[i * 4 + 2] = __expf(v2 - s_Max[2]) * s_Inv[2];
            s_alpha[i * 4 + 3] = __expf(v3 - s_Max[3]) * s_Inv[3];
        }
        __syncthreads();
        int i = 0;
        for (; i + 4 <= cnt; i += 4) {
            int s0 = s_src[i], s1 = s_src[i + 1], s2 = s_src[i + 2], s3 = s_src[i + 3];
            float a0 = s_alpha[i * 4 + h],       a1 = s_alpha[(i + 1) * 4 + h];
            float a2 = s_alpha[(i + 2) * 4 + h], a3 = s_alpha[(i + 3) * 4 + h];
            float z0 = g_z[(size_t)s0 * F_ + tid];
            float z1 = g_z[(size_t)s1 * F_ + tid];
            float z2 = g_z[(size_t)s2 * F_ + tid];
            float z3 = g_z[(size_t)s3 * F_ + tid];
            acc += a0 * z0; acc += a1 * z1; acc += a2 * z2; acc += a3 * z3;
        }
        for (; i < cnt; i++) {
            acc += s_alpha[i * 4 + h] * g_z[(size_t)s_src[i] * F_ + tid];
        }
    }
    float v = acc + b[tid];
    g_emb[(size_t)m * NF + (size_t)n * F_ + tid] = v > 0.f ? v : expm1f(v);
}

// ---------------------------------------------------------------------------
// Semantic attention scores via packed f32x2 FMA; M metapaths folded.
// 256 threads: k = tid&127, half = tid>>7 owns nodes half*4..+3.
// ---------------------------------------------------------------------------
__global__ void k_zerow() { if (threadIdx.x < 4) g_wsum[threadIdx.x] = 0.f; }

template <int M>
__global__ void __launch_bounds__(256) k_wscore(int base_sel,
                                                const float* __restrict__ W1,
                                                const float* __restrict__ b1,
                                                const float* __restrict__ w2) {
    extern __shared__ __align__(16) float smem[];
    float* sW1 = smem;                  // F_*SAH_
    float* sz  = smem + F_ * SAH_;      // M*SAN*F_
    int tid = threadIdx.x;
    int k = tid & 127, half = tid >> 7;
    for (int i = tid; i < F_ * SAH_; i += 256) sW1[i] = W1[i];
    const float* base = base_sel ? g_hl : g_emb;
    int node0 = blockIdx.x * SAN;
#pragma unroll
    for (int m = 0; m < M; m++)
        for (int i = tid; i < SAN * F_; i += 256) {
            int r = i >> 8, f = i & 255;
            sz[m * SAN * F_ + i] =
                (node0 + r < N_) ? base[(size_t)m * NF + (size_t)(node0 + r) * F_ + f] : 0.f;
        }
    __syncthreads();

    unsigned long long acc[M][4];
#pragma unroll
    for (int m = 0; m < M; m++)
#pragma unroll
        for (int j = 0; j < 4; j++) acc[m][j] = 0ull;

    for (int f = 0; f < F_; f += 4) {
        float w0 = sW1[f * SAH_ + k];
        float w1 = sW1[(f + 1) * SAH_ + k];
        float w2v = sW1[(f + 2) * SAH_ + k];
        float w3 = sW1[(f + 3) * SAH_ + k];
        unsigned long long wp01 = packf2(w0, w1);
        unsigned long long wp23 = packf2(w2v, w3);
#pragma unroll
        for (int m = 0; m < M; m++) {
#pragma unroll
            for (int j = 0; j < 4; j++) {
                const ulonglong2 zv =
                    *(const ulonglong2*)&sz[m * SAN * F_ + (half * 4 + j) * F_ + f];
                fma2(acc[m][j], zv.x, wp01);
                fma2(acc[m][j], zv.y, wp23);
            }
        }
    }

    float b1k = b1[k], w2k = w2[k];
    float accm[M];
#pragma unroll
    for (int m = 0; m < M; m++) accm[m] = 0.f;
#pragma unroll
    for (int m = 0; m < M; m++)
#pragma unroll
        for (int j = 0; j < 4; j++) {
            if (node0 + half * 4 + j < N_) {
                float a = unpack_sum(acc[m][j]) + b1k;
                accm[m] += tanhf(a) * w2k;
            }
        }

    __shared__ float sred[8];
    int lane = tid & 31, warp = tid >> 5;
#pragma unroll
    for (int m = 0; m < M; m++) {
        float v = accm[m];
#pragma unroll
        for (int o = 16; o > 0; o >>= 1) v += __shfl_down_sync(0xffffffffu, v, o);
        if (lane == 0) sred[warp] = v;
        __syncthreads();
        if (tid == 0) {
            float t = 0.f;
#pragma unroll
            for (int w = 0; w < 8; w++) t += sred[w];
            atomicAdd(&g_wsum[m], t);
        }
        __syncthreads();
    }
}

__global__ void k_beta(int M) {
    if (threadIdx.x == 0) {
        float w[3];
        float mx = -1e30f;
        for (int m = 0; m < M; m++) { w[m] = g_wsum[m] / (float)N_; mx = fmaxf(mx, w[m]); }
        float s = 0.f;
        for (int m = 0; m < M; m++) { w[m] = __expf(w[m] - mx); s += w[m]; }
        for (int m = 0; m < M; m++) g_beta[m] = w[m] / s;
    }
}

__global__ void k_combine(int base_sel, int M, int out_sel) {
    int i = blockIdx.x * 256 + threadIdx.x;
    if (i >= N_ * F_) return;
    const float* base = (base_sel == 0) ? g_emb : g_hl;
    float acc = 0.f;
    for (int m = 0; m < M; m++) acc += g_beta[m] * base[(size_t)m * NF + i];
    float* out = (out_sel == 0) ? g_hl : (out_sel == 1 ? g_hl + NF : g_hfin);
    out[i] = acc;
}

// ---------------------------------------------------------------------------
// logits = h_final @ pred_W + pred_b
// ---------------------------------------------------------------------------
__global__ void k_pred(const float* __restrict__ W, const float* __restrict__ b,
                       float* __restrict__ out) {
    __shared__ float sW[F_ * OUT_];
    int tid = threadIdx.x;
    for (int i = tid; i < F_ * OUT_; i += 256) sW[i] = W[i];
    __syncthreads();
    int node = blockIdx.x * 16 + (tid >> 4);
    int o = tid & 15;
    if (node >= N_) return;
    const float* hr = g_hfin + (size_t)node * F_;
    float acc = b[o];
#pragma unroll 8
    for (int f = 0; f < F_; f++) acc += hr[f] * sW[f * OUT_ + o];
    out[(size_t)node * OUT_ + o] = acc;
}

__global__ void k_copy(float* __restrict__ out) {
    int i = blockIdx.x * 256 + threadIdx.x;
    if (i < N_ * F_) out[i] = g_hfin[i];
}

// ---------------------------------------------------------------------------
// Host launcher — graph-capturable (kernel launches only)
// ---------------------------------------------------------------------------
extern "C" void kernel_launch(void* const* d_in, const int* in_sizes, int n_in,
                              void* d_out, int out_size) {
    const float* h = (const float*)d_in[0];
    const int* srcs[4] = {(const int*)d_in[1], (const int*)d_in[3], (const int*)d_in[5], (const int*)d_in[7]};
    const int* dsts[4] = {(const int*)d_in[2], (const int*)d_in[4], (const int*)d_in[6], (const int*)d_in[8]};
    int Eg[4] = {in_sizes[1], in_sizes[3], in_sizes[5], in_sizes[7]};
    const float* fcW = (const float*)d_in[10];
    const float* W[2]    = {(const float*)d_in[11], (const float*)d_in[18]};
    const float* al[2]   = {(const float*)d_in[12], (const float*)d_in[19]};
    const float* ar[2]   = {(const float*)d_in[13], (const float*)d_in[20]};
    const float* bb[2]   = {(const float*)d_in[14], (const float*)d_in[21]};
    const float* saW1[2] = {(const float*)d_in[15], (const float*)d_in[22]};
    const float* sab1[2] = {(const float*)d_in[16], (const float*)d_in[23]};
    const float* saw2[2] = {(const float*)d_in[17], (const float*)d_in[24]};
    const float* saW1f = (const float*)d_in[25];
    const float* sab1f = (const float*)d_in[26];
    const float* saw2f = (const float*)d_in[27];
    const float* predW = (const float*)d_in[28];
    const float* predb = (const float*)d_in[29];
    float* out = (float*)d_out;

    const int WS3 = (F_ * SAH_ + 3 * SAN * F_) * 4;
    const int WS2 = (F_ * SAH_ + 2 * SAN * F_) * 4;
    cudaFuncSetAttribute(k_wscore<3>, cudaFuncAttributeMaxDynamicSharedMemorySize, WS3);
    cudaFuncSetAttribute(k_wscore<2>, cudaFuncAttributeMaxDynamicSharedMemorySize, WS2);

    k_fc<<<(N_ + 15) / 16, 256>>>(h, fcW);

    // Build CSR for the 4 graphs (g0,g1 reused by both layers)
    for (int g = 0; g < 4; g++) {
        int E = Eg[g];
        k_zerocnt<<<(N_ + 255) / 256, 256>>>();
        k_hist<<<(E + 255) / 256, 256>>>(dsts[g], E);
        k_scan<<<1, 1024>>>(g);
        k_scatter<<<(E + 255) / 256, 256>>>(srcs[g], dsts[g], E, g);
    }

    const int graphsel[2][3] = {{0, 1, 2}, {0, 1, 3}};
    for (int L = 0; L < 2; L++) {
        for (int m = 0; m < 3; m++) {
            int g = graphsel[L][m];
            k_z<<<(N_ + 63) / 64, 256>>>(W[L] + (size_t)m * HID_ * F_);
            k_eler<<<N_, 128>>>(al[L] + m * F_, ar[L] + m * F_);
            k_conv<<<N_, 256>>>(g, bb[L] + m * F_, m);
        }
        k_zerow<<<1, 32>>>();
        k_wscore<3><<<(N_ + SAN - 1) / SAN, 256, WS3>>>(0, saW1[L], sab1[L], saw2[L]);
        k_beta<<<1, 32>>>(3);
        k_combine<<<(N_ * F_ + 255) / 256, 256>>>(0, 3, L);
    }

    k_zerow<<<1, 32>>>();
    k_wscore<2><<<(N_ + SAN - 1) / SAN, 256, WS2>>>(1, saW1f, sab1f, saw2f);
    k_beta<<<1, 32>>>(2);
    k_combine<<<(N_ * F_ + 255) / 256, 256>>>(1, 2, 2);

    k_pred<<<(N_ + 15) / 16, 256>>>(predW, predb, out);
    if (out_size >= N_ * (OUT_ + F_))
        k_copy<<<(N_ * F_ + 255) / 256, 256>>>(out + (size_t)N_ * OUT_);
}

// round 3
// speedup vs baseline: 1.9192x; 1.3922x over previous
#include <cuda_runtime.h>
#include <math.h>
#include <float.h>

// ---------------------------------------------------------------------------
// Problem constants
// ---------------------------------------------------------------------------
constexpr int N_   = 50000;
constexpr int IN_  = 128;
constexpr int HID_ = 64;
constexpr int H_   = 4;
constexpr int F_   = 256;    // H*D
constexpr int OUT_ = 16;
constexpr int SAH_ = 128;
constexpr int EMAX_ = 800000;

constexpr int SAN = 8;                       // nodes per wscore block
constexpr size_t NF = (size_t)N_ * F_;
constexpr int SCB_N = (N_ + 255) / 256;      // 196 scan blocks

// ---------------------------------------------------------------------------
// Device scratch (static — no cudaMalloc allowed)
// ---------------------------------------------------------------------------
__device__ float g_x[(size_t)N_ * HID_];
__device__ float g_z[NF];
__device__ __align__(16) float g_el[N_ * H_];
__device__ __align__(16) float g_er[N_ * H_];
__device__ float g_emb[3 * NF];
__device__ float g_hl[2 * NF];
__device__ float g_hfin[NF];
__device__ float g_wsum[4];
__device__ float g_beta[4];

// CSR scratch
__device__ int g_rowptr[4][N_ + 1];
__device__ int g_esrc[4][EMAX_];
__device__ int g_cnt[N_];
__device__ int g_cursor[N_];
__device__ int g_bsum[256];
__device__ int g_boff[256];

// ---------------------------------------------------------------------------
// f32x2 packed-FMA helpers (Blackwell FFMA2 — only reachable via PTX)
// ---------------------------------------------------------------------------
__device__ __forceinline__ void fma2(unsigned long long& acc,
                                     unsigned long long a, unsigned long long b) {
    asm("fma.rn.f32x2 %0, %1, %2, %0;" : "+l"(acc) : "l"(a), "l"(b));
}
__device__ __forceinline__ unsigned long long packf2(float lo, float hi) {
    unsigned long long r;
    asm("mov.b64 %0, {%1,%2};" : "=l"(r) : "f"(lo), "f"(hi));
    return r;
}
__device__ __forceinline__ float unpack_sum(unsigned long long p) {
    float lo, hi;
    asm("mov.b64 {%0,%1}, %2;" : "=f"(lo), "=f"(hi) : "l"(p));
    return lo + hi;
}

// ---------------------------------------------------------------------------
// x = h @ fc_W   [N,128] @ [128,64]
// ---------------------------------------------------------------------------
__global__ void k_fc(const float* __restrict__ h, const float* __restrict__ W) {
    __shared__ __align__(16) float sW[IN_ * HID_];
    __shared__ __align__(16) float sh[16 * IN_];
    int tid = threadIdx.x;
    for (int i = tid; i < IN_ * HID_; i += 256) sW[i] = W[i];
    int row0 = blockIdx.x * 16;
    for (int i = tid; i < 16 * IN_; i += 256) {
        int r = i >> 7, k = i & 127;
        sh[i] = (row0 + r < N_) ? h[(size_t)(row0 + r) * IN_ + k] : 0.f;
    }
    __syncthreads();
    int col = tid & 63;
    for (int rr = tid >> 6; rr < 16; rr += 4) {
        float acc = 0.f;
#pragma unroll
        for (int k = 0; k < IN_; k += 4) {
            float4 hv = *(const float4*)&sh[rr * IN_ + k];
            acc += hv.x * sW[k * HID_ + col] + hv.y * sW[(k + 1) * HID_ + col]
                 + hv.z * sW[(k + 2) * HID_ + col] + hv.w * sW[(k + 3) * HID_ + col];
        }
        if (row0 + rr < N_) g_x[(size_t)(row0 + rr) * HID_ + col] = acc;
    }
}

// ---------------------------------------------------------------------------
// z = x @ W_m   [N,64] @ [64,256]
// ---------------------------------------------------------------------------
__global__ void k_z(const float* __restrict__ W) {
    int c = threadIdx.x;
    float wreg[HID_];
#pragma unroll
    for (int k = 0; k < HID_; k++) wreg[k] = W[k * F_ + c];
    __shared__ __align__(16) float sx[64 * HID_];
    int row0 = blockIdx.x * 64;
    for (int i = threadIdx.x; i < 64 * HID_; i += 256) {
        int r = i >> 6, k = i & 63;
        sx[i] = (row0 + r < N_) ? g_x[(size_t)(row0 + r) * HID_ + k] : 0.f;
    }
    __syncthreads();
    int rmax = min(64, N_ - row0);
    for (int r = 0; r < rmax; r++) {
        float acc = 0.f;
#pragma unroll
        for (int k = 0; k < HID_; k += 4) {
            float4 xv = *(const float4*)&sx[r * HID_ + k];
            acc += xv.x * wreg[k] + xv.y * wreg[k + 1] + xv.z * wreg[k + 2] + xv.w * wreg[k + 3];
        }
        g_z[(size_t)(row0 + r) * F_ + c] = acc;
    }
}

// ---------------------------------------------------------------------------
// el/er — warp per node, segmented 8-lane reduction
// ---------------------------------------------------------------------------
__global__ void __launch_bounds__(256) k_eler(const float* __restrict__ al,
                                              const float* __restrict__ ar) {
    __shared__ __align__(16) float sal[F_];
    __shared__ __align__(16) float sar[F_];
    int tid = threadIdx.x;
    sal[tid] = al[tid];
    sar[tid] = ar[tid];
    __syncthreads();
    int lane = tid & 31, w = tid >> 5;
    int n = blockIdx.x * 8 + w;
    if (n >= N_) return;
    const float4* zp = (const float4*)(g_z + (size_t)n * F_ + lane * 8);
    float4 z0 = zp[0], z1 = zp[1];
    const float4* ap = (const float4*)(sal + lane * 8);
    const float4* rp = (const float4*)(sar + lane * 8);
    float4 a0 = ap[0], a1 = ap[1], r0 = rp[0], r1 = rp[1];
    float a = z0.x * a0.x + z0.y * a0.y + z0.z * a0.z + z0.w * a0.w
            + z1.x * a1.x + z1.y * a1.y + z1.z * a1.z + z1.w * a1.w;
    float b = z0.x * r0.x + z0.y * r0.y + z0.z * r0.z + z0.w * r0.w
            + z1.x * r1.x + z1.y * r1.y + z1.z * r1.z + z1.w * r1.w;
#pragma unroll
    for (int o = 1; o < 8; o <<= 1) {
        a += __shfl_xor_sync(0xffffffffu, a, o);
        b += __shfl_xor_sync(0xffffffffu, b, o);
    }
    if ((lane & 7) == 0) {
        int h = lane >> 3;
        g_el[n * H_ + h] = a;
        g_er[n * H_ + h] = b;
    }
}

// ---------------------------------------------------------------------------
// CSR construction
// ---------------------------------------------------------------------------
__global__ void k_zerocnt() {
    int i = blockIdx.x * 256 + threadIdx.x;
    if (i < N_) g_cnt[i] = 0;
}
__global__ void k_hist(const int* __restrict__ dst, int E) {
    int i = blockIdx.x * 256 + threadIdx.x;
    if (i < E) atomicAdd(&g_cnt[dst[i]], 1);
}

__device__ __forceinline__ int block_scan_excl(int v, int tid, int* total) {
    int lane = tid & 31, w = tid >> 5;
    int x = v;
#pragma unroll
    for (int o = 1; o < 32; o <<= 1) {
        int y = __shfl_up_sync(0xffffffffu, x, o);
        if (lane >= o) x += y;
    }
    __shared__ int ws[8];
    if (lane == 31) ws[w] = x;
    __syncthreads();
    if (w == 0) {
        int s = (lane < 8) ? ws[lane] : 0;
#pragma unroll
        for (int o = 1; o < 8; o <<= 1) {
            int y = __shfl_up_sync(0xffffffffu, s, o);
            if (lane >= o) s += y;
        }
        if (lane < 8) ws[lane] = s;
    }
    __syncthreads();
    int base = (w > 0) ? ws[w - 1] : 0;
    *total = ws[7];
    return base + x - v;
}

__global__ void k_scan1(int g) {
    int tid = threadIdx.x, b = blockIdx.x;
    int i = b * 256 + tid;
    int v = (i < N_) ? g_cnt[i] : 0;
    int total;
    int excl = block_scan_excl(v, tid, &total);
    if (i < N_) g_rowptr[g][i] = excl;
    if (tid == 0) g_bsum[b] = total;
}
__global__ void k_scan2(int g) {
    int tid = threadIdx.x;
    int v = (tid < SCB_N) ? g_bsum[tid] : 0;
    int total;
    int excl = block_scan_excl(v, tid, &total);
    g_boff[tid] = excl;
    if (tid == 0) g_rowptr[g][N_] = total;
}
__global__ void k_scan3(int g) {
    int i = blockIdx.x * 256 + threadIdx.x;
    if (i < N_) {
        int r = g_rowptr[g][i] + g_boff[i >> 8];
        g_rowptr[g][i] = r;
        g_cursor[i] = r;
    }
}
__global__ void k_scatter(const int* __restrict__ src, const int* __restrict__ dst,
                          int E, int g) {
    int i = blockIdx.x * 256 + threadIdx.x;
    if (i >= E) return;
    int d = dst[i];
    int pos = atomicAdd(&g_cursor[d], 1);
    g_esrc[g][pos] = src[i];
}

// ---------------------------------------------------------------------------
// Fused GAT conv — WARP per dst node. Lane l owns features l*8..l*8+7
// (single head h = l>>3 → one alpha per lane per edge).
// ---------------------------------------------------------------------------
__global__ void __launch_bounds__(256) k_conv(int g, const float* __restrict__ bias, int m) {
    __shared__ int s_src[8][32];
    __shared__ __align__(16) float4 s_alpha[8][32];

    int tid = threadIdx.x, lane = tid & 31, w = tid >> 5;
    int n = blockIdx.x * 8 + w;
    if (n >= N_) return;

    int e0 = g_rowptr[g][n], e1 = g_rowptr[g][n + 1];
    int deg = e1 - e0;
    const int* __restrict__ esrc = g_esrc[g];

    float4 ern = *(const float4*)(g_er + n * 4);
    int hsel = lane >> 3;
    float acc[8] = {0.f, 0.f, 0.f, 0.f, 0.f, 0.f, 0.f, 0.f};

    if (deg > 0 && deg <= 32) {
        int s = -1;
        float v0 = -FLT_MAX, v1 = -FLT_MAX, v2 = -FLT_MAX, v3 = -FLT_MAX;
        if (lane < deg) {
            s = esrc[e0 + lane];
            float4 els = *(const float4*)(g_el + s * 4);
            v0 = els.x + ern.x; v0 = v0 > 0.f ? v0 : 0.2f * v0;
            v1 = els.y + ern.y; v1 = v1 > 0.f ? v1 : 0.2f * v1;
            v2 = els.z + ern.z; v2 = v2 > 0.f ? v2 : 0.2f * v2;
            v3 = els.w + ern.w; v3 = v3 > 0.f ? v3 : 0.2f * v3;
        }
        float m0 = v0, m1 = v1, m2 = v2, m3 = v3;
#pragma unroll
        for (int o = 16; o > 0; o >>= 1) {
            m0 = fmaxf(m0, __shfl_xor_sync(0xffffffffu, m0, o));
            m1 = fmaxf(m1, __shfl_xor_sync(0xffffffffu, m1, o));
            m2 = fmaxf(m2, __shfl_xor_sync(0xffffffffu, m2, o));
            m3 = fmaxf(m3, __shfl_xor_sync(0xffffffffu, m3, o));
        }
        float e0f = (lane < deg) ? __expf(v0 - m0) : 0.f;
        float e1f = (lane < deg) ? __expf(v1 - m1) : 0.f;
        float e2f = (lane < deg) ? __expf(v2 - m2) : 0.f;
        float e3f = (lane < deg) ? __expf(v3 - m3) : 0.f;
        float s0 = e0f, s1 = e1f, s2 = e2f, s3 = e3f;
#pragma unroll
        for (int o = 16; o > 0; o >>= 1) {
            s0 += __shfl_xor_sync(0xffffffffu, s0, o);
            s1 += __shfl_xor_sync(0xffffffffu, s1, o);
            s2 += __shfl_xor_sync(0xffffffffu, s2, o);
            s3 += __shfl_xor_sync(0xffffffffu, s3, o);
        }
        s_src[w][lane] = s;
        s_alpha[w][lane] = make_float4(e0f / s0, e1f / s1, e2f / s2, e3f / s3);
        __syncwarp();
        for (int i = 0; i < deg; i++) {
            int si = s_src[w][i];
            float a = ((const float*)&s_alpha[w][i])[hsel];
            const float4* zp = (const float4*)(g_z + (size_t)si * F_ + lane * 8);
            float4 za = zp[0], zb = zp[1];
            acc[0] += a * za.x; acc[1] += a * za.y; acc[2] += a * za.z; acc[3] += a * za.w;
            acc[4] += a * zb.x; acc[5] += a * zb.y; acc[6] += a * zb.z; acc[7] += a * zb.w;
        }
    } else if (deg > 32) {
        // online softmax stats (every lane has >=1 edge since deg>32)
        float mx[4] = {-FLT_MAX, -FLT_MAX, -FLT_MAX, -FLT_MAX};
        float sm[4] = {0.f, 0.f, 0.f, 0.f};
        for (int e = e0 + lane; e < e1; e += 32) {
            int s = esrc[e];
            float4 els = *(const float4*)(g_el + s * 4);
            float v[4];
            v[0] = els.x + ern.x; v[1] = els.y + ern.y;
            v[2] = els.z + ern.z; v[3] = els.w + ern.w;
#pragma unroll
            for (int h = 0; h < 4; h++) {
                float vv = v[h] > 0.f ? v[h] : 0.2f * v[h];
                float nm = fmaxf(mx[h], vv);
                sm[h] = sm[h] * __expf(mx[h] - nm) + __expf(vv - nm);
                mx[h] = nm;
            }
        }
#pragma unroll
        for (int h = 0; h < 4; h++) {
#pragma unroll
            for (int o = 16; o > 0; o >>= 1) {
                float om = __shfl_xor_sync(0xffffffffu, mx[h], o);
                float os = __shfl_xor_sync(0xffffffffu, sm[h], o);
                float nm = fmaxf(mx[h], om);
                sm[h] = sm[h] * __expf(mx[h] - nm) + os * __expf(om - nm);
                mx[h] = nm;
            }
        }
        float inv[4];
#pragma unroll
        for (int h = 0; h < 4; h++) inv[h] = 1.f / sm[h];

        for (int base = 0; base < deg; base += 32) {
            int cnt = min(32, deg - base);
            int s = -1;
            float4 al4 = make_float4(0.f, 0.f, 0.f, 0.f);
            if (lane < cnt) {
                s = esrc[e0 + base + lane];
                float4 els = *(const float4*)(g_el + s * 4);
                float v0 = els.x + ern.x; v0 = v0 > 0.f ? v0 : 0.2f * v0;
                float v1 = els.y + ern.y; v1 = v1 > 0.f ? v1 : 0.2f * v1;
                float v2 = els.z + ern.z; v2 = v2 > 0.f ? v2 : 0.2f * v2;
                float v3 = els.w + ern.w; v3 = v3 > 0.f ? v3 : 0.2f * v3;
                al4 = make_float4(__expf(v0 - mx[0]) * inv[0], __expf(v1 - mx[1]) * inv[1],
                                  __expf(v2 - mx[2]) * inv[2], __expf(v3 - mx[3]) * inv[3]);
            }
            __syncwarp();
            s_src[w][lane] = s;
            s_alpha[w][lane] = al4;
            __syncwarp();
            for (int i = 0; i < cnt; i++) {
                int si = s_src[w][i];
                float a = ((const float*)&s_alpha[w][i])[hsel];
                const float4* zp = (const float4*)(g_z + (size_t)si * F_ + lane * 8);
                float4 za = zp[0], zb = zp[1];
                acc[0] += a * za.x; acc[1] += a * za.y; acc[2] += a * za.z; acc[3] += a * za.w;
                acc[4] += a * zb.x; acc[5] += a * zb.y; acc[6] += a * zb.z; acc[7] += a * zb.w;
            }
        }
    }

    const float4* bp = (const float4*)(bias + lane * 8);
    float4 b0 = bp[0], b1 = bp[1];
    float o[8];
    o[0] = acc[0] + b0.x; o[1] = acc[1] + b0.y; o[2] = acc[2] + b0.z; o[3] = acc[3] + b0.w;
    o[4] = acc[4] + b1.x; o[5] = acc[5] + b1.y; o[6] = acc[6] + b1.z; o[7] = acc[7] + b1.w;
#pragma unroll
    for (int j = 0; j < 8; j++) o[j] = o[j] > 0.f ? o[j] : expm1f(o[j]);
    float4* op = (float4*)(g_emb + (size_t)m * NF + (size_t)n * F_ + lane * 8);
    op[0] = make_float4(o[0], o[1], o[2], o[3]);
    op[1] = make_float4(o[4], o[5], o[6], o[7]);
}

// ---------------------------------------------------------------------------
// Semantic attention scores (packed f32x2 FMA)
// ---------------------------------------------------------------------------
__global__ void k_zerow() { if (threadIdx.x < 4) g_wsum[threadIdx.x] = 0.f; }

template <int M>
__global__ void __launch_bounds__(256) k_wscore(int base_sel,
                                                const float* __restrict__ W1,
                                                const float* __restrict__ b1,
                                                const float* __restrict__ w2) {
    extern __shared__ __align__(16) float smem[];
    float* sW1 = smem;
    float* sz  = smem + F_ * SAH_;
    int tid = threadIdx.x;
    int k = tid & 127, half = tid >> 7;
    for (int i = tid; i < F_ * SAH_; i += 256) sW1[i] = W1[i];
    const float* base = base_sel ? g_hl : g_emb;
    int node0 = blockIdx.x * SAN;
#pragma unroll
    for (int m = 0; m < M; m++)
        for (int i = tid; i < SAN * F_; i += 256) {
            int r = i >> 8, f = i & 255;
            sz[m * SAN * F_ + i] =
                (node0 + r < N_) ? base[(size_t)m * NF + (size_t)(node0 + r) * F_ + f] : 0.f;
        }
    __syncthreads();

    unsigned long long acc[M][4];
#pragma unroll
    for (int m = 0; m < M; m++)
#pragma unroll
        for (int j = 0; j < 4; j++) acc[m][j] = 0ull;

    for (int f = 0; f < F_; f += 4) {
        float w0 = sW1[f * SAH_ + k];
        float w1 = sW1[(f + 1) * SAH_ + k];
        float w2v = sW1[(f + 2) * SAH_ + k];
        float w3 = sW1[(f + 3) * SAH_ + k];
        unsigned long long wp01 = packf2(w0, w1);
        unsigned long long wp23 = packf2(w2v, w3);
#pragma unroll
        for (int m = 0; m < M; m++) {
#pragma unroll
            for (int j = 0; j < 4; j++) {
                const ulonglong2 zv =
                    *(const ulonglong2*)&sz[m * SAN * F_ + (half * 4 + j) * F_ + f];
                fma2(acc[m][j], zv.x, wp01);
                fma2(acc[m][j], zv.y, wp23);
            }
        }
    }

    float b1k = b1[k], w2k = w2[k];
    float accm[M];
#pragma unroll
    for (int m = 0; m < M; m++) accm[m] = 0.f;
#pragma unroll
    for (int m = 0; m < M; m++)
#pragma unroll
        for (int j = 0; j < 4; j++) {
            if (node0 + half * 4 + j < N_) {
                float a = unpack_sum(acc[m][j]) + b1k;
                accm[m] += tanhf(a) * w2k;
            }
        }

    __shared__ float sred[8];
    int lane = tid & 31, warp = tid >> 5;
#pragma unroll
    for (int m = 0; m < M; m++) {
        float v = accm[m];
#pragma unroll
        for (int o = 16; o > 0; o >>= 1) v += __shfl_down_sync(0xffffffffu, v, o);
        if (lane == 0) sred[warp] = v;
        __syncthreads();
        if (tid == 0) {
            float t = 0.f;
#pragma unroll
            for (int w = 0; w < 8; w++) t += sred[w];
            atomicAdd(&g_wsum[m], t);
        }
        __syncthreads();
    }
}

__global__ void k_beta(int M) {
    if (threadIdx.x == 0) {
        float w[3];
        float mx = -1e30f;
        for (int m = 0; m < M; m++) { w[m] = g_wsum[m] / (float)N_; mx = fmaxf(mx, w[m]); }
        float s = 0.f;
        for (int m = 0; m < M; m++) { w[m] = __expf(w[m] - mx); s += w[m]; }
        for (int m = 0; m < M; m++) g_beta[m] = w[m] / s;
    }
}

// out_sel: 0/1 -> g_hl slots, 2 -> g_hfin (+ optional duplicate to harness out)
__global__ void k_combine(int base_sel, int M, int out_sel, float* __restrict__ dup) {
    int i = blockIdx.x * 256 + threadIdx.x;
    if (i >= N_ * F_) return;
    const float* base = (base_sel == 0) ? g_emb : g_hl;
    float acc = 0.f;
    for (int m = 0; m < M; m++) acc += g_beta[m] * base[(size_t)m * NF + i];
    float* out = (out_sel == 0) ? g_hl : (out_sel == 1 ? g_hl + NF : g_hfin);
    out[i] = acc;
    if (dup) dup[i] = acc;
}

// ---------------------------------------------------------------------------
// logits = h_final @ pred_W + pred_b
// ---------------------------------------------------------------------------
__global__ void k_pred(const float* __restrict__ W, const float* __restrict__ b,
                       float* __restrict__ out) {
    __shared__ float sW[F_ * OUT_];
    int tid = threadIdx.x;
    for (int i = tid; i < F_ * OUT_; i += 256) sW[i] = W[i];
    __syncthreads();
    int node = blockIdx.x * 16 + (tid >> 4);
    int o = tid & 15;
    if (node >= N_) return;
    const float* hr = g_hfin + (size_t)node * F_;
    float acc = b[o];
#pragma unroll 8
    for (int f = 0; f < F_; f++) acc += hr[f] * sW[f * OUT_ + o];
    out[(size_t)node * OUT_ + o] = acc;
}

// ---------------------------------------------------------------------------
// Host launcher — graph-capturable
// ---------------------------------------------------------------------------
extern "C" void kernel_launch(void* const* d_in, const int* in_sizes, int n_in,
                              void* d_out, int out_size) {
    const float* h = (const float*)d_in[0];
    const int* srcs[4] = {(const int*)d_in[1], (const int*)d_in[3], (const int*)d_in[5], (const int*)d_in[7]};
    const int* dsts[4] = {(const int*)d_in[2], (const int*)d_in[4], (const int*)d_in[6], (const int*)d_in[8]};
    int Eg[4] = {in_sizes[1], in_sizes[3], in_sizes[5], in_sizes[7]};
    const float* fcW = (const float*)d_in[10];
    const float* W[2]    = {(const float*)d_in[11], (const float*)d_in[18]};
    const float* al[2]   = {(const float*)d_in[12], (const float*)d_in[19]};
    const float* ar[2]   = {(const float*)d_in[13], (const float*)d_in[20]};
    const float* bb[2]   = {(const float*)d_in[14], (const float*)d_in[21]};
    const float* saW1[2] = {(const float*)d_in[15], (const float*)d_in[22]};
    const float* sab1[2] = {(const float*)d_in[16], (const float*)d_in[23]};
    const float* saw2[2] = {(const float*)d_in[17], (const float*)d_in[24]};
    const float* saW1f = (const float*)d_in[25];
    const float* sab1f = (const float*)d_in[26];
    const float* saw2f = (const float*)d_in[27];
    const float* predW = (const float*)d_in[28];
    const float* predb = (const float*)d_in[29];
    float* out = (float*)d_out;

    const int WS3 = (F_ * SAH_ + 3 * SAN * F_) * 4;
    const int WS2 = (F_ * SAH_ + 2 * SAN * F_) * 4;
    cudaFuncSetAttribute(k_wscore<3>, cudaFuncAttributeMaxDynamicSharedMemorySize, WS3);
    cudaFuncSetAttribute(k_wscore<2>, cudaFuncAttributeMaxDynamicSharedMemorySize, WS2);

    k_fc<<<(N_ + 15) / 16, 256>>>(h, fcW);

    // Build CSR for the 4 graphs
    for (int g = 0; g < 4; g++) {
        int E = Eg[g];
        k_zerocnt<<<SCB_N, 256>>>();
        k_hist<<<(E + 255) / 256, 256>>>(dsts[g], E);
        k_scan1<<<SCB_N, 256>>>(g);
        k_scan2<<<1, 256>>>(g);
        k_scan3<<<SCB_N, 256>>>(g);
        k_scatter<<<(E + 255) / 256, 256>>>(srcs[g], dsts[g], E, g);
    }

    const int graphsel[2][3] = {{0, 1, 2}, {0, 1, 3}};
    for (int L = 0; L < 2; L++) {
        for (int m = 0; m < 3; m++) {
            int g = graphsel[L][m];
            k_z<<<(N_ + 63) / 64, 256>>>(W[L] + (size_t)m * HID_ * F_);
            k_eler<<<(N_ + 7) / 8, 256>>>(al[L] + m * F_, ar[L] + m * F_);
            k_conv<<<(N_ + 7) / 8, 256>>>(g, bb[L] + m * F_, m);
        }
        k_zerow<<<1, 32>>>();
        k_wscore<3><<<(N_ + SAN - 1) / SAN, 256, WS3>>>(0, saW1[L], sab1[L], saw2[L]);
        k_beta<<<1, 32>>>(3);
        k_combine<<<(N_ * F_ + 255) / 256, 256>>>(0, 3, L, nullptr);
    }

    k_zerow<<<1, 32>>>();
    k_wscore<2><<<(N_ + SAN - 1) / SAN, 256, WS2>>>(1, saW1f, sab1f, saw2f);
    k_beta<<<1, 32>>>(2);
    float* dup = (out_size >= N_ * (OUT_ + F_)) ? out + (size_t)N_ * OUT_ : nullptr;
    k_combine<<<(N_ * F_ + 255) / 256, 256>>>(1, 2, 2, dup);

    k_pred<<<(N_ + 15) / 16, 256>>>(predW, predb, out);
}

// round 4
// speedup vs baseline: 3.7210x; 1.9388x over previous
#include <cuda_runtime.h>
#include <math.h>
#include <float.h>

// ---------------------------------------------------------------------------
// Problem constants
// ---------------------------------------------------------------------------
constexpr int N_   = 50000;
constexpr int IN_  = 128;
constexpr int HID_ = 64;
constexpr int H_   = 4;
constexpr int F_   = 256;    // H*D
constexpr int OUT_ = 16;
constexpr int SAH_ = 128;
constexpr int EMAX_ = 800000;

constexpr size_t NF = (size_t)N_ * F_;
constexpr int SCB_N = (N_ + 255) / 256;      // 196 scan blocks
constexpr int WSB_N = (N_ + 127) / 128;      // 391 wscore node-tiles

// ---------------------------------------------------------------------------
// Device scratch (static — no cudaMalloc allowed)
// ---------------------------------------------------------------------------
__device__ float g_x[(size_t)N_ * HID_];
__device__ float g_z[NF];
__device__ __align__(16) float g_el[N_ * H_];
__device__ __align__(16) float g_er[N_ * H_];
__device__ float g_emb[3 * NF];
__device__ float g_hl[2 * NF];
__device__ float g_hfin[NF];
__device__ float g_wsum[4];
__device__ float g_beta[4];
__device__ unsigned int g_W1t[SAH_ * F_];    // tf32 bits, [k][f]

// CSR scratch
__device__ int g_rowptr[4][N_ + 1];
__device__ int g_esrc[4][EMAX_];
__device__ int g_cnt[N_];
__device__ int g_cursor[N_];
__device__ int g_bsum[256];
__device__ int g_boff[256];

// ---------------------------------------------------------------------------
// Low-level helpers
// ---------------------------------------------------------------------------
__device__ __forceinline__ unsigned int f2tf32(float f) {
    unsigned int r;
    asm("cvt.rna.tf32.f32 %0, %1;" : "=r"(r) : "f"(f));
    return r;
}
__device__ __forceinline__ float tanh_fast(float x) {
    float r;
    asm("tanh.approx.f32 %0, %1;" : "=f"(r) : "f"(x));
    return r;
}
__device__ __forceinline__ void mma_tf32(float& d0, float& d1, float& d2, float& d3,
                                         unsigned int a0, unsigned int a1,
                                         unsigned int a2, unsigned int a3,
                                         unsigned int b0, unsigned int b1) {
    asm("mma.sync.aligned.m16n8k8.row.col.f32.tf32.tf32.f32 "
        "{%0,%1,%2,%3}, {%4,%5,%6,%7}, {%8,%9}, {%0,%1,%2,%3};"
        : "+f"(d0), "+f"(d1), "+f"(d2), "+f"(d3)
        : "r"(a0), "r"(a1), "r"(a2), "r"(a3), "r"(b0), "r"(b1));
}

// ---------------------------------------------------------------------------
// x = h @ fc_W   [N,128] @ [128,64]
// ---------------------------------------------------------------------------
__global__ void k_fc(const float* __restrict__ h, const float* __restrict__ W) {
    __shared__ __align__(16) float sW[IN_ * HID_];
    __shared__ __align__(16) float sh[16 * IN_];
    int tid = threadIdx.x;
    for (int i = tid; i < IN_ * HID_; i += 256) sW[i] = W[i];
    int row0 = blockIdx.x * 16;
    for (int i = tid; i < 16 * IN_; i += 256) {
        int r = i >> 7, k = i & 127;
        sh[i] = (row0 + r < N_) ? h[(size_t)(row0 + r) * IN_ + k] : 0.f;
    }
    __syncthreads();
    int col = tid & 63;
    for (int rr = tid >> 6; rr < 16; rr += 4) {
        float acc = 0.f;
#pragma unroll
        for (int k = 0; k < IN_; k += 4) {
            float4 hv = *(const float4*)&sh[rr * IN_ + k];
            acc += hv.x * sW[k * HID_ + col] + hv.y * sW[(k + 1) * HID_ + col]
                 + hv.z * sW[(k + 2) * HID_ + col] + hv.w * sW[(k + 3) * HID_ + col];
        }
        if (row0 + rr < N_) g_x[(size_t)(row0 + rr) * HID_ + col] = acc;
    }
}

// ---------------------------------------------------------------------------
// z = x @ W_m   [N,64] @ [64,256]
// ---------------------------------------------------------------------------
__global__ void k_z(const float* __restrict__ W) {
    int c = threadIdx.x;
    float wreg[HID_];
#pragma unroll
    for (int k = 0; k < HID_; k++) wreg[k] = W[k * F_ + c];
    __shared__ __align__(16) float sx[64 * HID_];
    int row0 = blockIdx.x * 64;
    for (int i = threadIdx.x; i < 64 * HID_; i += 256) {
        int r = i >> 6, k = i & 63;
        sx[i] = (row0 + r < N_) ? g_x[(size_t)(row0 + r) * HID_ + k] : 0.f;
    }
    __syncthreads();
    int rmax = min(64, N_ - row0);
    for (int r = 0; r < rmax; r++) {
        float acc = 0.f;
#pragma unroll
        for (int k = 0; k < HID_; k += 4) {
            float4 xv = *(const float4*)&sx[r * HID_ + k];
            acc += xv.x * wreg[k] + xv.y * wreg[k + 1] + xv.z * wreg[k + 2] + xv.w * wreg[k + 3];
        }
        g_z[(size_t)(row0 + r) * F_ + c] = acc;
    }
}

// ---------------------------------------------------------------------------
// el/er — warp per node, segmented 8-lane reduction
// ---------------------------------------------------------------------------
__global__ void __launch_bounds__(256) k_eler(const float* __restrict__ al,
                                              const float* __restrict__ ar) {
    __shared__ __align__(16) float sal[F_];
    __shared__ __align__(16) float sar[F_];
    int tid = threadIdx.x;
    sal[tid] = al[tid];
    sar[tid] = ar[tid];
    __syncthreads();
    int lane = tid & 31, w = tid >> 5;
    int n = blockIdx.x * 8 + w;
    if (n >= N_) return;
    const float4* zp = (const float4*)(g_z + (size_t)n * F_ + lane * 8);
    float4 z0 = zp[0], z1 = zp[1];
    const float4* ap = (const float4*)(sal + lane * 8);
    const float4* rp = (const float4*)(sar + lane * 8);
    float4 a0 = ap[0], a1 = ap[1], r0 = rp[0], r1 = rp[1];
    float a = z0.x * a0.x + z0.y * a0.y + z0.z * a0.z + z0.w * a0.w
            + z1.x * a1.x + z1.y * a1.y + z1.z * a1.z + z1.w * a1.w;
    float b = z0.x * r0.x + z0.y * r0.y + z0.z * r0.z + z0.w * r0.w
            + z1.x * r1.x + z1.y * r1.y + z1.z * r1.z + z1.w * r1.w;
#pragma unroll
    for (int o = 1; o < 8; o <<= 1) {
        a += __shfl_xor_sync(0xffffffffu, a, o);
        b += __shfl_xor_sync(0xffffffffu, b, o);
    }
    if ((lane & 7) == 0) {
        int h = lane >> 3;
        g_el[n * H_ + h] = a;
        g_er[n * H_ + h] = b;
    }
}

// ---------------------------------------------------------------------------
// CSR construction
// ---------------------------------------------------------------------------
__global__ void k_zerocnt() {
    int i = blockIdx.x * 256 + threadIdx.x;
    if (i < N_) g_cnt[i] = 0;
}
__global__ void k_hist(const int* __restrict__ dst, int E) {
    int i = blockIdx.x * 256 + threadIdx.x;
    if (i < E) atomicAdd(&g_cnt[dst[i]], 1);
}

__device__ __forceinline__ int block_scan_excl(int v, int tid, int* total) {
    int lane = tid & 31, w = tid >> 5;
    int x = v;
#pragma unroll
    for (int o = 1; o < 32; o <<= 1) {
        int y = __shfl_up_sync(0xffffffffu, x, o);
        if (lane >= o) x += y;
    }
    __shared__ int ws[8];
    if (lane == 31) ws[w] = x;
    __syncthreads();
    if (w == 0) {
        int s = (lane < 8) ? ws[lane] : 0;
#pragma unroll
        for (int o = 1; o < 8; o <<= 1) {
            int y = __shfl_up_sync(0xffffffffu, s, o);
            if (lane >= o) s += y;
        }
        if (lane < 8) ws[lane] = s;
    }
    __syncthreads();
    int base = (w > 0) ? ws[w - 1] : 0;
    *total = ws[7];
    return base + x - v;
}

__global__ void k_scan1(int g) {
    int tid = threadIdx.x, b = blockIdx.x;
    int i = b * 256 + tid;
    int v = (i < N_) ? g_cnt[i] : 0;
    int total;
    int excl = block_scan_excl(v, tid, &total);
    if (i < N_) g_rowptr[g][i] = excl;
    if (tid == 0) g_bsum[b] = total;
}
__global__ void k_scan2(int g) {
    int tid = threadIdx.x;
    int v = (tid < SCB_N) ? g_bsum[tid] : 0;
    int total;
    int excl = block_scan_excl(v, tid, &total);
    g_boff[tid] = excl;
    if (tid == 0) g_rowptr[g][N_] = total;
}
__global__ void k_scan3(int g) {
    int i = blockIdx.x * 256 + threadIdx.x;
    if (i < N_) {
        int r = g_rowptr[g][i] + g_boff[i >> 8];
        g_rowptr[g][i] = r;
        g_cursor[i] = r;
    }
}
__global__ void k_scatter(const int* __restrict__ src, const int* __restrict__ dst,
                          int E, int g) {
    int i = blockIdx.x * 256 + threadIdx.x;
    if (i >= E) return;
    int d = dst[i];
    int pos = atomicAdd(&g_cursor[d], 1);
    g_esrc[g][pos] = src[i];
}

// ---------------------------------------------------------------------------
// Fused GAT conv — WARP per dst node.
// ---------------------------------------------------------------------------
__global__ void __launch_bounds__(256) k_conv(int g, const float* __restrict__ bias, int m) {
    __shared__ int s_src[8][32];
    __shared__ __align__(16) float4 s_alpha[8][32];

    int tid = threadIdx.x, lane = tid & 31, w = tid >> 5;
    int n = blockIdx.x * 8 + w;
    if (n >= N_) return;

    int e0 = g_rowptr[g][n], e1 = g_rowptr[g][n + 1];
    int deg = e1 - e0;
    const int* __restrict__ esrc = g_esrc[g];

    float4 ern = *(const float4*)(g_er + n * 4);
    int hsel = lane >> 3;
    float acc[8] = {0.f, 0.f, 0.f, 0.f, 0.f, 0.f, 0.f, 0.f};

    if (deg > 0 && deg <= 32) {
        int s = -1;
        float v0 = -FLT_MAX, v1 = -FLT_MAX, v2 = -FLT_MAX, v3 = -FLT_MAX;
        if (lane < deg) {
            s = esrc[e0 + lane];
            float4 els = *(const float4*)(g_el + s * 4);
            v0 = els.x + ern.x; v0 = v0 > 0.f ? v0 : 0.2f * v0;
            v1 = els.y + ern.y; v1 = v1 > 0.f ? v1 : 0.2f * v1;
            v2 = els.z + ern.z; v2 = v2 > 0.f ? v2 : 0.2f * v2;
            v3 = els.w + ern.w; v3 = v3 > 0.f ? v3 : 0.2f * v3;
        }
        float m0 = v0, m1 = v1, m2 = v2, m3 = v3;
#pragma unroll
        for (int o = 16; o > 0; o >>= 1) {
            m0 = fmaxf(m0, __shfl_xor_sync(0xffffffffu, m0, o));
            m1 = fmaxf(m1, __shfl_xor_sync(0xffffffffu, m1, o));
            m2 = fmaxf(m2, __shfl_xor_sync(0xffffffffu, m2, o));
            m3 = fmaxf(m3, __shfl_xor_sync(0xffffffffu, m3, o));
        }
        float e0f = (lane < deg) ? __expf(v0 - m0) : 0.f;
        float e1f = (lane < deg) ? __expf(v1 - m1) : 0.f;
        float e2f = (lane < deg) ? __expf(v2 - m2) : 0.f;
        float e3f = (lane < deg) ? __expf(v3 - m3) : 0.f;
        float s0 = e0f, s1 = e1f, s2 = e2f, s3 = e3f;
#pragma unroll
        for (int o = 16; o > 0; o >>= 1) {
            s0 += __shfl_xor_sync(0xffffffffu, s0, o);
            s1 += __shfl_xor_sync(0xffffffffu, s1, o);
            s2 += __shfl_xor_sync(0xffffffffu, s2, o);
            s3 += __shfl_xor_sync(0xffffffffu, s3, o);
        }
        s_src[w][lane] = s;
        s_alpha[w][lane] = make_float4(e0f / s0, e1f / s1, e2f / s2, e3f / s3);
        __syncwarp();
        for (int i = 0; i < deg; i++) {
            int si = s_src[w][i];
            float a = ((const float*)&s_alpha[w][i])[hsel];
            const float4* zp = (const float4*)(g_z + (size_t)si * F_ + lane * 8);
            float4 za = zp[0], zb = zp[1];
            acc[0] += a * za.x; acc[1] += a * za.y; acc[2] += a * za.z; acc[3] += a * za.w;
            acc[4] += a * zb.x; acc[5] += a * zb.y; acc[6] += a * zb.z; acc[7] += a * zb.w;
        }
    } else if (deg > 32) {
        float mx[4] = {-FLT_MAX, -FLT_MAX, -FLT_MAX, -FLT_MAX};
        float sm[4] = {0.f, 0.f, 0.f, 0.f};
        for (int e = e0 + lane; e < e1; e += 32) {
            int s = esrc[e];
            float4 els = *(const float4*)(g_el + s * 4);
            float v[4];
            v[0] = els.x + ern.x; v[1] = els.y + ern.y;
            v[2] = els.z + ern.z; v[3] = els.w + ern.w;
#pragma unroll
            for (int h = 0; h < 4; h++) {
                float vv = v[h] > 0.f ? v[h] : 0.2f * v[h];
                float nm = fmaxf(mx[h], vv);
                sm[h] = sm[h] * __expf(mx[h] - nm) + __expf(vv - nm);
                mx[h] = nm;
            }
        }
#pragma unroll
        for (int h = 0; h < 4; h++) {
#pragma unroll
            for (int o = 16; o > 0; o >>= 1) {
                float om = __shfl_xor_sync(0xffffffffu, mx[h], o);
                float os = __shfl_xor_sync(0xffffffffu, sm[h], o);
                float nm = fmaxf(mx[h], om);
                sm[h] = sm[h] * __expf(mx[h] - nm) + os * __expf(om - nm);
                mx[h] = nm;
            }
        }
        float inv[4];
#pragma unroll
        for (int h = 0; h < 4; h++) inv[h] = 1.f / sm[h];

        for (int base = 0; base < deg; base += 32) {
            int cnt = min(32, deg - base);
            int s = -1;
            float4 al4 = make_float4(0.f, 0.f, 0.f, 0.f);
            if (lane < cnt) {
                s = esrc[e0 + base + lane];
                float4 els = *(const float4*)(g_el + s * 4);
                float v0 = els.x + ern.x; v0 = v0 > 0.f ? v0 : 0.2f * v0;
                float v1 = els.y + ern.y; v1 = v1 > 0.f ? v1 : 0.2f * v1;
                float v2 = els.z + ern.z; v2 = v2 > 0.f ? v2 : 0.2f * v2;
                float v3 = els.w + ern.w; v3 = v3 > 0.f ? v3 : 0.2f * v3;
                al4 = make_float4(__expf(v0 - mx[0]) * inv[0], __expf(v1 - mx[1]) * inv[1],
                                  __expf(v2 - mx[2]) * inv[2], __expf(v3 - mx[3]) * inv[3]);
            }
            __syncwarp();
            s_src[w][lane] = s;
            s_alpha[w][lane] = al4;
            __syncwarp();
            for (int i = 0; i < cnt; i++) {
                int si = s_src[w][i];
                float a = ((const float*)&s_alpha[w][i])[hsel];
                const float4* zp = (const float4*)(g_z + (size_t)si * F_ + lane * 8);
                float4 za = zp[0], zb = zp[1];
                acc[0] += a * za.x; acc[1] += a * za.y; acc[2] += a * za.z; acc[3] += a * za.w;
                acc[4] += a * zb.x; acc[5] += a * zb.y; acc[6] += a * zb.z; acc[7] += a * zb.w;
            }
        }
    }

    const float4* bp = (const float4*)(bias + lane * 8);
    float4 b0 = bp[0], b1 = bp[1];
    float o[8];
    o[0] = acc[0] + b0.x; o[1] = acc[1] + b0.y; o[2] = acc[2] + b0.z; o[3] = acc[3] + b0.w;
    o[4] = acc[4] + b1.x; o[5] = acc[5] + b1.y; o[6] = acc[6] + b1.z; o[7] = acc[7] + b1.w;
#pragma unroll
    for (int j = 0; j < 8; j++) o[j] = o[j] > 0.f ? o[j] : expm1f(o[j]);
    float4* op = (float4*)(g_emb + (size_t)m * NF + (size_t)n * F_ + lane * 8);
    op[0] = make_float4(o[0], o[1], o[2], o[3]);
    op[1] = make_float4(o[4], o[5], o[6], o[7]);
}

// ---------------------------------------------------------------------------
// W1 prep: transpose + tf32-convert, and zero wsum
// ---------------------------------------------------------------------------
__global__ void k_prepW1(const float* __restrict__ W1) {
    int j = blockIdx.x * 256 + threadIdx.x;
    if (j < SAH_ * F_) {
        int k = j >> 8, f = j & 255;
        g_W1t[j] = f2tf32(W1[f * SAH_ + k]);
    }
    if (blockIdx.x == 0 && threadIdx.x < 4) g_wsum[threadIdx.x] = 0.f;
}

// ---------------------------------------------------------------------------
// Semantic-attention score GEMM on tensor cores (tf32 mma.sync).
// Block tile: 128 nodes x 128 SAH cols, K=256. 8 warps, warp tile 16x128.
// Epilogue: wsum[m] += sum tanh(C + b1)*w2 over valid rows.
// ---------------------------------------------------------------------------
__global__ void __launch_bounds__(256) k_wscore_tc(int base_sel,
                                                   const float* __restrict__ b1,
                                                   const float* __restrict__ w2) {
    __shared__ unsigned int sA[128][36];
    __shared__ unsigned int sB[128][36];
    __shared__ float s_b1[SAH_], s_w2[SAH_];
    __shared__ float sred[8];

    int tid = threadIdx.x, lane = tid & 31, w = tid >> 5;
    int m = blockIdx.y;
    int n0 = blockIdx.x * 128;
    const float* Z = (base_sel ? g_hl : g_emb) + (size_t)m * NF;
    if (tid < SAH_) { s_b1[tid] = b1[tid]; s_w2[tid] = w2[tid]; }

    float acc[16][4];
#pragma unroll
    for (int t = 0; t < 16; t++)
#pragma unroll
        for (int j = 0; j < 4; j++) acc[t][j] = 0.f;

    int g4 = lane >> 2, tg = lane & 3;
    int ar0 = w * 16 + g4, ar1 = ar0 + 8;

    for (int f0 = 0; f0 < F_; f0 += 32) {
        __syncthreads();
        // stage A (z rows, fp32 -> tf32)
        for (int i = tid; i < 128 * 8; i += 256) {
            int r = i >> 3, q = i & 7;
            int n = n0 + r;
            float4 v = make_float4(0.f, 0.f, 0.f, 0.f);
            if (n < N_) v = *(const float4*)&Z[(size_t)n * F_ + f0 + q * 4];
            sA[r][q * 4 + 0] = f2tf32(v.x);
            sA[r][q * 4 + 1] = f2tf32(v.y);
            sA[r][q * 4 + 2] = f2tf32(v.z);
            sA[r][q * 4 + 3] = f2tf32(v.w);
        }
        // stage B (pre-transposed tf32 W1)
        for (int i = tid; i < 128 * 8; i += 256) {
            int k = i >> 3, q = i & 7;
            uint4 v = *(const uint4*)&g_W1t[k * F_ + f0 + q * 4];
            sB[k][q * 4 + 0] = v.x;
            sB[k][q * 4 + 1] = v.y;
            sB[k][q * 4 + 2] = v.z;
            sB[k][q * 4 + 3] = v.w;
        }
        __syncthreads();
#pragma unroll
        for (int kk = 0; kk < 32; kk += 8) {
            unsigned int a0 = sA[ar0][kk + tg];
            unsigned int a1 = sA[ar1][kk + tg];
            unsigned int a2 = sA[ar0][kk + tg + 4];
            unsigned int a3 = sA[ar1][kk + tg + 4];
#pragma unroll
            for (int t = 0; t < 16; t++) {
                int c = t * 8 + g4;
                unsigned int b0v = sB[c][kk + tg];
                unsigned int b1v = sB[c][kk + tg + 4];
                mma_tf32(acc[t][0], acc[t][1], acc[t][2], acc[t][3],
                         a0, a1, a2, a3, b0v, b1v);
            }
        }
    }

    // epilogue: tanh + dot(w2), masked by node validity
    float tot = 0.f;
    bool v0 = (n0 + ar0) < N_, v1 = (n0 + ar1) < N_;
#pragma unroll
    for (int t = 0; t < 16; t++) {
        int c0 = t * 8 + tg * 2, c1 = c0 + 1;
        float bb0 = s_b1[c0], bb1 = s_b1[c1];
        float ww0 = s_w2[c0], ww1 = s_w2[c1];
        if (v0) tot += tanh_fast(acc[t][0] + bb0) * ww0 + tanh_fast(acc[t][1] + bb1) * ww1;
        if (v1) tot += tanh_fast(acc[t][2] + bb0) * ww0 + tanh_fast(acc[t][3] + bb1) * ww1;
    }
#pragma unroll
    for (int o = 16; o > 0; o >>= 1) tot += __shfl_xor_sync(0xffffffffu, tot, o);
    if (lane == 0) sred[w] = tot;
    __syncthreads();
    if (tid == 0) {
        float s = 0.f;
#pragma unroll
        for (int i = 0; i < 8; i++) s += sred[i];
        atomicAdd(&g_wsum[m], s);
    }
}

__global__ void k_beta(int M) {
    if (threadIdx.x == 0) {
        float w[3];
        float mx = -1e30f;
        for (int m = 0; m < M; m++) { w[m] = g_wsum[m] / (float)N_; mx = fmaxf(mx, w[m]); }
        float s = 0.f;
        for (int m = 0; m < M; m++) { w[m] = __expf(w[m] - mx); s += w[m]; }
        for (int m = 0; m < M; m++) g_beta[m] = w[m] / s;
    }
}

// out_sel: 0/1 -> g_hl slots, 2 -> g_hfin (+ optional duplicate to harness out)
__global__ void k_combine(int base_sel, int M, int out_sel, float* __restrict__ dup) {
    int i = blockIdx.x * 256 + threadIdx.x;
    if (i >= N_ * F_) return;
    const float* base = (base_sel == 0) ? g_emb : g_hl;
    float acc = 0.f;
    for (int m = 0; m < M; m++) acc += g_beta[m] * base[(size_t)m * NF + i];
    float* out = (out_sel == 0) ? g_hl : (out_sel == 1 ? g_hl + NF : g_hfin);
    out[i] = acc;
    if (dup) dup[i] = acc;
}

// ---------------------------------------------------------------------------
// logits = h_final @ pred_W + pred_b
// ---------------------------------------------------------------------------
__global__ void k_pred(const float* __restrict__ W, const float* __restrict__ b,
                       float* __restrict__ out) {
    __shared__ float sW[F_ * OUT_];
    int tid = threadIdx.x;
    for (int i = tid; i < F_ * OUT_; i += 256) sW[i] = W[i];
    __syncthreads();
    int node = blockIdx.x * 16 + (tid >> 4);
    int o = tid & 15;
    if (node >= N_) return;
    const float* hr = g_hfin + (size_t)node * F_;
    float acc = b[o];
#pragma unroll 8
    for (int f = 0; f < F_; f++) acc += hr[f] * sW[f * OUT_ + o];
    out[(size_t)node * OUT_ + o] = acc;
}

// ---------------------------------------------------------------------------
// Host launcher — graph-capturable
// ---------------------------------------------------------------------------
extern "C" void kernel_launch(void* const* d_in, const int* in_sizes, int n_in,
                              void* d_out, int out_size) {
    const float* h = (const float*)d_in[0];
    const int* srcs[4] = {(const int*)d_in[1], (const int*)d_in[3], (const int*)d_in[5], (const int*)d_in[7]};
    const int* dsts[4] = {(const int*)d_in[2], (const int*)d_in[4], (const int*)d_in[6], (const int*)d_in[8]};
    int Eg[4] = {in_sizes[1], in_sizes[3], in_sizes[5], in_sizes[7]};
    const float* fcW = (const float*)d_in[10];
    const float* W[2]    = {(const float*)d_in[11], (const float*)d_in[18]};
    const float* al[2]   = {(const float*)d_in[12], (const float*)d_in[19]};
    const float* ar[2]   = {(const float*)d_in[13], (const float*)d_in[20]};
    const float* bb[2]   = {(const float*)d_in[14], (const float*)d_in[21]};
    const float* saW1[2] = {(const float*)d_in[15], (const float*)d_in[22]};
    const float* sab1[2] = {(const float*)d_in[16], (const float*)d_in[23]};
    const float* saw2[2] = {(const float*)d_in[17], (const float*)d_in[24]};
    const float* saW1f = (const float*)d_in[25];
    const float* sab1f = (const float*)d_in[26];
    const float* saw2f = (const float*)d_in[27];
    const float* predW = (const float*)d_in[28];
    const float* predb = (const float*)d_in[29];
    float* out = (float*)d_out;

    k_fc<<<(N_ + 15) / 16, 256>>>(h, fcW);

    // Build CSR for the 4 graphs
    for (int g = 0; g < 4; g++) {
        int E = Eg[g];
        k_zerocnt<<<SCB_N, 256>>>();
        k_hist<<<(E + 255) / 256, 256>>>(dsts[g], E);
        k_scan1<<<SCB_N, 256>>>(g);
        k_scan2<<<1, 256>>>(g);
        k_scan3<<<SCB_N, 256>>>(g);
        k_scatter<<<(E + 255) / 256, 256>>>(srcs[g], dsts[g], E, g);
    }

    const int graphsel[2][3] = {{0, 1, 2}, {0, 1, 3}};
    for (int L = 0; L < 2; L++) {
        for (int m = 0; m < 3; m++) {
            int g = graphsel[L][m];
            k_z<<<(N_ + 63) / 64, 256>>>(W[L] + (size_t)m * HID_ * F_);
            k_eler<<<(N_ + 7) / 8, 256>>>(al[L] + m * F_, ar[L] + m * F_);
            k_conv<<<(N_ + 7) / 8, 256>>>(g, bb[L] + m * F_, m);
        }
        k_prepW1<<<(SAH_ * F_ + 255) / 256, 256>>>(saW1[L]);
        k_wscore_tc<<<dim3(WSB_N, 3), 256>>>(0, sab1[L], saw2[L]);
        k_beta<<<1, 32>>>(3);
        k_combine<<<(N_ * F_ + 255) / 256, 256>>>(0, 3, L, nullptr);
    }

    k_prepW1<<<(SAH_ * F_ + 255) / 256, 256>>>(saW1f);
    k_wscore_tc<<<dim3(WSB_N, 2), 256>>>(1, sab1f, saw2f);
    k_beta<<<1, 32>>>(2);
    float* dup = (out_size >= N_ * (OUT_ + F_)) ? out + (size_t)N_ * OUT_ : nullptr;
    k_combine<<<(N_ * F_ + 255) / 256, 256>>>(1, 2, 2, dup);

    k_pred<<<(N_ + 15) / 16, 256>>>(predW, predb, out);
}

// round 5
// speedup vs baseline: 3.8602x; 1.0374x over previous
#include <cuda_runtime.h>
#include <math.h>
#include <float.h>

// ---------------------------------------------------------------------------
// Problem constants
// ---------------------------------------------------------------------------
constexpr int N_   = 50000;
constexpr int IN_  = 128;
constexpr int HID_ = 64;
constexpr int H_   = 4;
constexpr int F_   = 256;    // H*D
constexpr int OUT_ = 16;
constexpr int SAH_ = 128;
constexpr int EMAX_ = 800000;

constexpr size_t NF = (size_t)N_ * F_;
constexpr int SCB_N = (N_ + 255) / 256;      // 196 scan blocks
constexpr int WSB_N = (N_ + 127) / 128;      // 391 wscore node-tiles

// ---------------------------------------------------------------------------
// Device scratch (static — no cudaMalloc allowed)
// ---------------------------------------------------------------------------
__device__ float g_x[(size_t)N_ * HID_];
__device__ float g_z[NF];
__device__ __align__(16) float g_el[N_ * H_];
__device__ __align__(16) float g_er[N_ * H_];
__device__ float g_emb[3 * NF];
__device__ float g_hl[2 * NF];
__device__ float g_hfin[NF];
__device__ float g_wsum[4];
__device__ float g_beta[4];
__device__ unsigned int g_W1t[SAH_ * F_];    // tf32 bits, [k][f]

// CSR scratch
__device__ int g_rowptr[4][N_ + 1];
__device__ int g_esrc[4][EMAX_];
__device__ int g_cnt[N_];
__device__ int g_cursor[N_];
__device__ int g_bsum[256];
__device__ int g_boff[256];

// ---------------------------------------------------------------------------
// Low-level helpers
// ---------------------------------------------------------------------------
__device__ __forceinline__ unsigned int f2tf32(float f) {
    unsigned int r;
    asm("cvt.rna.tf32.f32 %0, %1;" : "=r"(r) : "f"(f));
    return r;
}
__device__ __forceinline__ float tanh_fast(float x) {
    float r;
    asm("tanh.approx.f32 %0, %1;" : "=f"(r) : "f"(x));
    return r;
}
__device__ __forceinline__ void mma_tf32(float& d0, float& d1, float& d2, float& d3,
                                         unsigned int a0, unsigned int a1,
                                         unsigned int a2, unsigned int a3,
                                         unsigned int b0, unsigned int b1) {
    asm("mma.sync.aligned.m16n8k8.row.col.f32.tf32.tf32.f32 "
        "{%0,%1,%2,%3}, {%4,%5,%6,%7}, {%8,%9}, {%0,%1,%2,%3};"
        : "+f"(d0), "+f"(d1), "+f"(d2), "+f"(d3)
        : "r"(a0), "r"(a1), "r"(a2), "r"(a3), "r"(b0), "r"(b1));
}

// ---------------------------------------------------------------------------
// x = h @ fc_W   [N,128] @ [128,64]
// ---------------------------------------------------------------------------
__global__ void k_fc(const float* __restrict__ h, const float* __restrict__ W) {
    __shared__ __align__(16) float sW[IN_ * HID_];
    __shared__ __align__(16) float sh[16 * IN_];
    int tid = threadIdx.x;
    for (int i = tid; i < IN_ * HID_; i += 256) sW[i] = W[i];
    int row0 = blockIdx.x * 16;
    for (int i = tid; i < 16 * IN_; i += 256) {
        int r = i >> 7, k = i & 127;
        sh[i] = (row0 + r < N_) ? h[(size_t)(row0 + r) * IN_ + k] : 0.f;
    }
    __syncthreads();
    int col = tid & 63;
    for (int rr = tid >> 6; rr < 16; rr += 4) {
        float acc = 0.f;
#pragma unroll
        for (int k = 0; k < IN_; k += 4) {
            float4 hv = *(const float4*)&sh[rr * IN_ + k];
            acc += hv.x * sW[k * HID_ + col] + hv.y * sW[(k + 1) * HID_ + col]
                 + hv.z * sW[(k + 2) * HID_ + col] + hv.w * sW[(k + 3) * HID_ + col];
        }
        if (row0 + rr < N_) g_x[(size_t)(row0 + rr) * HID_ + col] = acc;
    }
}

// ---------------------------------------------------------------------------
// z = x @ W_m   [N,64] @ [64,256]
// ---------------------------------------------------------------------------
__global__ void k_z(const float* __restrict__ W) {
    int c = threadIdx.x;
    float wreg[HID_];
#pragma unroll
    for (int k = 0; k < HID_; k++) wreg[k] = W[k * F_ + c];
    __shared__ __align__(16) float sx[64 * HID_];
    int row0 = blockIdx.x * 64;
    for (int i = threadIdx.x; i < 64 * HID_; i += 256) {
        int r = i >> 6, k = i & 63;
        sx[i] = (row0 + r < N_) ? g_x[(size_t)(row0 + r) * HID_ + k] : 0.f;
    }
    __syncthreads();
    int rmax = min(64, N_ - row0);
    for (int r = 0; r < rmax; r++) {
        float acc = 0.f;
#pragma unroll
        for (int k = 0; k < HID_; k += 4) {
            float4 xv = *(const float4*)&sx[r * HID_ + k];
            acc += xv.x * wreg[k] + xv.y * wreg[k + 1] + xv.z * wreg[k + 2] + xv.w * wreg[k + 3];
        }
        g_z[(size_t)(row0 + r) * F_ + c] = acc;
    }
}

// ---------------------------------------------------------------------------
// el/er — warp per node, segmented 8-lane reduction
// ---------------------------------------------------------------------------
__global__ void __launch_bounds__(256) k_eler(const float* __restrict__ al,
                                              const float* __restrict__ ar) {
    __shared__ __align__(16) float sal[F_];
    __shared__ __align__(16) float sar[F_];
    int tid = threadIdx.x;
    sal[tid] = al[tid];
    sar[tid] = ar[tid];
    __syncthreads();
    int lane = tid & 31, w = tid >> 5;
    int n = blockIdx.x * 8 + w;
    if (n >= N_) return;
    const float4* zp = (const float4*)(g_z + (size_t)n * F_ + lane * 8);
    float4 z0 = zp[0], z1 = zp[1];
    const float4* ap = (const float4*)(sal + lane * 8);
    const float4* rp = (const float4*)(sar + lane * 8);
    float4 a0 = ap[0], a1 = ap[1], r0 = rp[0], r1 = rp[1];
    float a = z0.x * a0.x + z0.y * a0.y + z0.z * a0.z + z0.w * a0.w
            + z1.x * a1.x + z1.y * a1.y + z1.z * a1.z + z1.w * a1.w;
    float b = z0.x * r0.x + z0.y * r0.y + z0.z * r0.z + z0.w * r0.w
            + z1.x * r1.x + z1.y * r1.y + z1.z * r1.z + z1.w * r1.w;
#pragma unroll
    for (int o = 1; o < 8; o <<= 1) {
        a += __shfl_xor_sync(0xffffffffu, a, o);
        b += __shfl_xor_sync(0xffffffffu, b, o);
    }
    if ((lane & 7) == 0) {
        int h = lane >> 3;
        g_el[n * H_ + h] = a;
        g_er[n * H_ + h] = b;
    }
}

// ---------------------------------------------------------------------------
// CSR construction
// ---------------------------------------------------------------------------
__global__ void k_zerocnt() {
    int i = blockIdx.x * 256 + threadIdx.x;
    if (i < N_) g_cnt[i] = 0;
}
__global__ void k_hist(const int* __restrict__ dst, int E) {
    int i = blockIdx.x * 256 + threadIdx.x;
    if (i < E) atomicAdd(&g_cnt[dst[i]], 1);
}

__device__ __forceinline__ int block_scan_excl(int v, int tid, int* total) {
    int lane = tid & 31, w = tid >> 5;
    int x = v;
#pragma unroll
    for (int o = 1; o < 32; o <<= 1) {
        int y = __shfl_up_sync(0xffffffffu, x, o);
        if (lane >= o) x += y;
    }
    __shared__ int ws[8];
    if (lane == 31) ws[w] = x;
    __syncthreads();
    if (w == 0) {
        int s = (lane < 8) ? ws[lane] : 0;
#pragma unroll
        for (int o = 1; o < 8; o <<= 1) {
            int y = __shfl_up_sync(0xffffffffu, s, o);
            if (lane >= o) s += y;
        }
        if (lane < 8) ws[lane] = s;
    }
    __syncthreads();
    int base = (w > 0) ? ws[w - 1] : 0;
    *total = ws[7];
    return base + x - v;
}

__global__ void k_scan1(int g) {
    int tid = threadIdx.x, b = blockIdx.x;
    int i = b * 256 + tid;
    int v = (i < N_) ? g_cnt[i] : 0;
    int total;
    int excl = block_scan_excl(v, tid, &total);
    if (i < N_) g_rowptr[g][i] = excl;
    if (tid == 0) g_bsum[b] = total;
}
__global__ void k_scan2(int g) {
    int tid = threadIdx.x;
    int v = (tid < SCB_N) ? g_bsum[tid] : 0;
    int total;
    int excl = block_scan_excl(v, tid, &total);
    g_boff[tid] = excl;
    if (tid == 0) g_rowptr[g][N_] = total;
}
__global__ void k_scan3(int g) {
    int i = blockIdx.x * 256 + threadIdx.x;
    if (i < N_) {
        int r = g_rowptr[g][i] + g_boff[i >> 8];
        g_rowptr[g][i] = r;
        g_cursor[i] = r;
    }
}
__global__ void k_scatter(const int* __restrict__ src, const int* __restrict__ dst,
                          int E, int g) {
    int i = blockIdx.x * 256 + threadIdx.x;
    if (i >= E) return;
    int d = dst[i];
    int pos = atomicAdd(&g_cursor[d], 1);
    g_esrc[g][pos] = src[i];
}

// ---------------------------------------------------------------------------
// Gather-accumulate with 4-edge unroll: 8 outstanding LDG.128 before FMAs.
// ---------------------------------------------------------------------------
__device__ __forceinline__ void gather_acc(const int* __restrict__ ssrc,
                                           const float4* __restrict__ salpha,
                                           int cnt, int hsel, int lane,
                                           float acc[8]) {
    int i = 0;
    for (; i + 4 <= cnt; i += 4) {
        int s0 = ssrc[i], s1 = ssrc[i + 1], s2 = ssrc[i + 2], s3 = ssrc[i + 3];
        float a0 = ((const float*)&salpha[i])[hsel];
        float a1 = ((const float*)&salpha[i + 1])[hsel];
        float a2 = ((const float*)&salpha[i + 2])[hsel];
        float a3 = ((const float*)&salpha[i + 3])[hsel];
        const float4* p0 = (const float4*)(g_z + (size_t)s0 * F_ + lane * 8);
        const float4* p1 = (const float4*)(g_z + (size_t)s1 * F_ + lane * 8);
        const float4* p2 = (const float4*)(g_z + (size_t)s2 * F_ + lane * 8);
        const float4* p3 = (const float4*)(g_z + (size_t)s3 * F_ + lane * 8);
        float4 x0 = p0[0], y0 = p0[1];
        float4 x1 = p1[0], y1 = p1[1];
        float4 x2 = p2[0], y2 = p2[1];
        float4 x3 = p3[0], y3 = p3[1];
        acc[0] += a0 * x0.x; acc[1] += a0 * x0.y; acc[2] += a0 * x0.z; acc[3] += a0 * x0.w;
        acc[4] += a0 * y0.x; acc[5] += a0 * y0.y; acc[6] += a0 * y0.z; acc[7] += a0 * y0.w;
        acc[0] += a1 * x1.x; acc[1] += a1 * x1.y; acc[2] += a1 * x1.z; acc[3] += a1 * x1.w;
        acc[4] += a1 * y1.x; acc[5] += a1 * y1.y; acc[6] += a1 * y1.z; acc[7] += a1 * y1.w;
        acc[0] += a2 * x2.x; acc[1] += a2 * x2.y; acc[2] += a2 * x2.z; acc[3] += a2 * x2.w;
        acc[4] += a2 * y2.x; acc[5] += a2 * y2.y; acc[6] += a2 * y2.z; acc[7] += a2 * y2.w;
        acc[0] += a3 * x3.x; acc[1] += a3 * x3.y; acc[2] += a3 * x3.z; acc[3] += a3 * x3.w;
        acc[4] += a3 * y3.x; acc[5] += a3 * y3.y; acc[6] += a3 * y3.z; acc[7] += a3 * y3.w;
    }
    for (; i < cnt; i++) {
        int si = ssrc[i];
        float a = ((const float*)&salpha[i])[hsel];
        const float4* zp = (const float4*)(g_z + (size_t)si * F_ + lane * 8);
        float4 za = zp[0], zb = zp[1];
        acc[0] += a * za.x; acc[1] += a * za.y; acc[2] += a * za.z; acc[3] += a * za.w;
        acc[4] += a * zb.x; acc[5] += a * zb.y; acc[6] += a * zb.z; acc[7] += a * zb.w;
    }
}

// ---------------------------------------------------------------------------
// Fused GAT conv — WARP per dst node.
// ---------------------------------------------------------------------------
__global__ void __launch_bounds__(256) k_conv(int g, const float* __restrict__ bias, int m) {
    __shared__ int s_src[8][32];
    __shared__ __align__(16) float4 s_alpha[8][32];

    int tid = threadIdx.x, lane = tid & 31, w = tid >> 5;
    int n = blockIdx.x * 8 + w;
    if (n >= N_) return;

    int e0 = g_rowptr[g][n], e1 = g_rowptr[g][n + 1];
    int deg = e1 - e0;
    const int* __restrict__ esrc = g_esrc[g];

    float4 ern = *(const float4*)(g_er + n * 4);
    int hsel = lane >> 3;
    float acc[8] = {0.f, 0.f, 0.f, 0.f, 0.f, 0.f, 0.f, 0.f};

    if (deg > 0 && deg <= 32) {
        int s = -1;
        float v0 = -FLT_MAX, v1 = -FLT_MAX, v2 = -FLT_MAX, v3 = -FLT_MAX;
        if (lane < deg) {
            s = esrc[e0 + lane];
            float4 els = *(const float4*)(g_el + s * 4);
            v0 = els.x + ern.x; v0 = v0 > 0.f ? v0 : 0.2f * v0;
            v1 = els.y + ern.y; v1 = v1 > 0.f ? v1 : 0.2f * v1;
            v2 = els.z + ern.z; v2 = v2 > 0.f ? v2 : 0.2f * v2;
            v3 = els.w + ern.w; v3 = v3 > 0.f ? v3 : 0.2f * v3;
        }
        float m0 = v0, m1 = v1, m2 = v2, m3 = v3;
#pragma unroll
        for (int o = 16; o > 0; o >>= 1) {
            m0 = fmaxf(m0, __shfl_xor_sync(0xffffffffu, m0, o));
            m1 = fmaxf(m1, __shfl_xor_sync(0xffffffffu, m1, o));
            m2 = fmaxf(m2, __shfl_xor_sync(0xffffffffu, m2, o));
            m3 = fmaxf(m3, __shfl_xor_sync(0xffffffffu, m3, o));
        }
        float e0f = (lane < deg) ? __expf(v0 - m0) : 0.f;
        float e1f = (lane < deg) ? __expf(v1 - m1) : 0.f;
        float e2f = (lane < deg) ? __expf(v2 - m2) : 0.f;
        float e3f = (lane < deg) ? __expf(v3 - m3) : 0.f;
        float s0 = e0f, s1 = e1f, s2 = e2f, s3 = e3f;
#pragma unroll
        for (int o = 16; o > 0; o >>= 1) {
            s0 += __shfl_xor_sync(0xffffffffu, s0, o);
            s1 += __shfl_xor_sync(0xffffffffu, s1, o);
            s2 += __shfl_xor_sync(0xffffffffu, s2, o);
            s3 += __shfl_xor_sync(0xffffffffu, s3, o);
        }
        s_src[w][lane] = s;
        s_alpha[w][lane] = make_float4(e0f / s0, e1f / s1, e2f / s2, e3f / s3);
        __syncwarp();
        gather_acc(s_src[w], s_alpha[w], deg, hsel, lane, acc);
    } else if (deg > 32) {
        float mx[4] = {-FLT_MAX, -FLT_MAX, -FLT_MAX, -FLT_MAX};
        float sm[4] = {0.f, 0.f, 0.f, 0.f};
        for (int e = e0 + lane; e < e1; e += 32) {
            int s = esrc[e];
            float4 els = *(const float4*)(g_el + s * 4);
            float v[4];
            v[0] = els.x + ern.x; v[1] = els.y + ern.y;
            v[2] = els.z + ern.z; v[3] = els.w + ern.w;
#pragma unroll
            for (int h = 0; h < 4; h++) {
                float vv = v[h] > 0.f ? v[h] : 0.2f * v[h];
                float nm = fmaxf(mx[h], vv);
                sm[h] = sm[h] * __expf(mx[h] - nm) + __expf(vv - nm);
                mx[h] = nm;
            }
        }
#pragma unroll
        for (int h = 0; h < 4; h++) {
#pragma unroll
            for (int o = 16; o > 0; o >>= 1) {
                float om = __shfl_xor_sync(0xffffffffu, mx[h], o);
                float os = __shfl_xor_sync(0xffffffffu, sm[h], o);
                float nm = fmaxf(mx[h], om);
                sm[h] = sm[h] * __expf(mx[h] - nm) + os * __expf(om - nm);
                mx[h] = nm;
            }
        }
        float inv[4];
#pragma unroll
        for (int h = 0; h < 4; h++) inv[h] = 1.f / sm[h];

        for (int base = 0; base < deg; base += 32) {
            int cnt = min(32, deg - base);
            int s = -1;
            float4 al4 = make_float4(0.f, 0.f, 0.f, 0.f);
            if (lane < cnt) {
                s = esrc[e0 + base + lane];
                float4 els = *(const float4*)(g_el + s * 4);
                float v0 = els.x + ern.x; v0 = v0 > 0.f ? v0 : 0.2f * v0;
                float v1 = els.y + ern.y; v1 = v1 > 0.f ? v1 : 0.2f * v1;
                float v2 = els.z + ern.z; v2 = v2 > 0.f ? v2 : 0.2f * v2;
                float v3 = els.w + ern.w; v3 = v3 > 0.f ? v3 : 0.2f * v3;
                al4 = make_float4(__expf(v0 - mx[0]) * inv[0], __expf(v1 - mx[1]) * inv[1],
                                  __expf(v2 - mx[2]) * inv[2], __expf(v3 - mx[3]) * inv[3]);
            }
            __syncwarp();
            s_src[w][lane] = s;
            s_alpha[w][lane] = al4;
            __syncwarp();
            gather_acc(s_src[w], s_alpha[w], cnt, hsel, lane, acc);
        }
    }

    const float4* bp = (const float4*)(bias + lane * 8);
    float4 b0 = bp[0], b1 = bp[1];
    float o[8];
    o[0] = acc[0] + b0.x; o[1] = acc[1] + b0.y; o[2] = acc[2] + b0.z; o[3] = acc[3] + b0.w;
    o[4] = acc[4] + b1.x; o[5] = acc[5] + b1.y; o[6] = acc[6] + b1.z; o[7] = acc[7] + b1.w;
#pragma unroll
    for (int j = 0; j < 8; j++) o[j] = o[j] > 0.f ? o[j] : expm1f(o[j]);
    float4* op = (float4*)(g_emb + (size_t)m * NF + (size_t)n * F_ + lane * 8);
    op[0] = make_float4(o[0], o[1], o[2], o[3]);
    op[1] = make_float4(o[4], o[5], o[6], o[7]);
}

// ---------------------------------------------------------------------------
// W1 prep: transpose + tf32-convert, and zero wsum
// ---------------------------------------------------------------------------
__global__ void k_prepW1(const float* __restrict__ W1) {
    int j = blockIdx.x * 256 + threadIdx.x;
    if (j < SAH_ * F_) {
        int k = j >> 8, f = j & 255;
        g_W1t[j] = f2tf32(W1[f * SAH_ + k]);
    }
    if (blockIdx.x == 0 && threadIdx.x < 4) g_wsum[threadIdx.x] = 0.f;
}

// ---------------------------------------------------------------------------
// Semantic-attention score GEMM on tensor cores (tf32 mma.sync).
// ---------------------------------------------------------------------------
__global__ void __launch_bounds__(256) k_wscore_tc(int base_sel,
                                                   const float* __restrict__ b1,
                                                   const float* __restrict__ w2) {
    __shared__ unsigned int sA[128][36];
    __shared__ unsigned int sB[128][36];
    __shared__ float s_b1[SAH_], s_w2[SAH_];
    __shared__ float sred[8];

    int tid = threadIdx.x, lane = tid & 31, w = tid >> 5;
    int m = blockIdx.y;
    int n0 = blockIdx.x * 128;
    const float* Z = (base_sel ? g_hl : g_emb) + (size_t)m * NF;
    if (tid < SAH_) { s_b1[tid] = b1[tid]; s_w2[tid] = w2[tid]; }

    float acc[16][4];
#pragma unroll
    for (int t = 0; t < 16; t++)
#pragma unroll
        for (int j = 0; j < 4; j++) acc[t][j] = 0.f;

    int g4 = lane >> 2, tg = lane & 3;
    int ar0 = w * 16 + g4, ar1 = ar0 + 8;

    for (int f0 = 0; f0 < F_; f0 += 32) {
        __syncthreads();
        for (int i = tid; i < 128 * 8; i += 256) {
            int r = i >> 3, q = i & 7;
            int n = n0 + r;
            float4 v = make_float4(0.f, 0.f, 0.f, 0.f);
            if (n < N_) v = *(const float4*)&Z[(size_t)n * F_ + f0 + q * 4];
            sA[r][q * 4 + 0] = f2tf32(v.x);
            sA[r][q * 4 + 1] = f2tf32(v.y);
            sA[r][q * 4 + 2] = f2tf32(v.z);
            sA[r][q * 4 + 3] = f2tf32(v.w);
        }
        for (int i = tid; i < 128 * 8; i += 256) {
            int k = i >> 3, q = i & 7;
            uint4 v = *(const uint4*)&g_W1t[k * F_ + f0 + q * 4];
            sB[k][q * 4 + 0] = v.x;
            sB[k][q * 4 + 1] = v.y;
            sB[k][q * 4 + 2] = v.z;
            sB[k][q * 4 + 3] = v.w;
        }
        __syncthreads();
#pragma unroll
        for (int kk = 0; kk < 32; kk += 8) {
            unsigned int a0 = sA[ar0][kk + tg];
            unsigned int a1 = sA[ar1][kk + tg];
            unsigned int a2 = sA[ar0][kk + tg + 4];
            unsigned int a3 = sA[ar1][kk + tg + 4];
#pragma unroll
            for (int t = 0; t < 16; t++) {
                int c = t * 8 + g4;
                unsigned int b0v = sB[c][kk + tg];
                unsigned int b1v = sB[c][kk + tg + 4];
                mma_tf32(acc[t][0], acc[t][1], acc[t][2], acc[t][3],
                         a0, a1, a2, a3, b0v, b1v);
            }
        }
    }

    float tot = 0.f;
    bool v0 = (n0 + ar0) < N_, v1 = (n0 + ar1) < N_;
#pragma unroll
    for (int t = 0; t < 16; t++) {
        int c0 = t * 8 + tg * 2, c1 = c0 + 1;
        float bb0 = s_b1[c0], bb1 = s_b1[c1];
        float ww0 = s_w2[c0], ww1 = s_w2[c1];
        if (v0) tot += tanh_fast(acc[t][0] + bb0) * ww0 + tanh_fast(acc[t][1] + bb1) * ww1;
        if (v1) tot += tanh_fast(acc[t][2] + bb0) * ww0 + tanh_fast(acc[t][3] + bb1) * ww1;
    }
#pragma unroll
    for (int o = 16; o > 0; o >>= 1) tot += __shfl_xor_sync(0xffffffffu, tot, o);
    if (lane == 0) sred[w] = tot;
    __syncthreads();
    if (tid == 0) {
        float s = 0.f;
#pragma unroll
        for (int i = 0; i < 8; i++) s += sred[i];
        atomicAdd(&g_wsum[m], s);
    }
}

__global__ void k_beta(int M) {
    if (threadIdx.x == 0) {
        float w[3];
        float mx = -1e30f;
        for (int m = 0; m < M; m++) { w[m] = g_wsum[m] / (float)N_; mx = fmaxf(mx, w[m]); }
        float s = 0.f;
        for (int m = 0; m < M; m++) { w[m] = __expf(w[m] - mx); s += w[m]; }
        for (int m = 0; m < M; m++) g_beta[m] = w[m] / s;
    }
}

// out_sel: 0/1 -> g_hl slots, 2 -> g_hfin (+ optional duplicate)
__global__ void k_combine(int base_sel, int M, int out_sel, float* __restrict__ dup) {
    size_t i = ((size_t)blockIdx.x * 256 + threadIdx.x) * 4;
    if (i >= NF) return;
    const float* base = (base_sel == 0) ? g_emb : g_hl;
    float b0 = g_beta[0], b1 = g_beta[1], b2 = g_beta[2];
    float4 v0 = *(const float4*)&base[i];
    float4 v1 = *(const float4*)&base[NF + i];
    float4 r;
    r.x = b0 * v0.x + b1 * v1.x;
    r.y = b0 * v0.y + b1 * v1.y;
    r.z = b0 * v0.z + b1 * v1.z;
    r.w = b0 * v0.w + b1 * v1.w;
    if (M == 3) {
        float4 v2 = *(const float4*)&base[2 * NF + i];
        r.x += b2 * v2.x; r.y += b2 * v2.y; r.z += b2 * v2.z; r.w += b2 * v2.w;
    }
    float* out = (out_sel == 0) ? g_hl : (out_sel == 1 ? g_hl + NF : g_hfin);
    *(float4*)&out[i] = r;
    if (dup) *(float4*)&dup[i] = r;
}

// ---------------------------------------------------------------------------
// logits = h_final @ pred_W + pred_b
// ---------------------------------------------------------------------------
__global__ void k_pred(const float* __restrict__ W, const float* __restrict__ b,
                       float* __restrict__ out) {
    __shared__ float sW[F_ * OUT_];
    int tid = threadIdx.x;
    for (int i = tid; i < F_ * OUT_; i += 256) sW[i] = W[i];
    __syncthreads();
    int node = blockIdx.x * 16 + (tid >> 4);
    int o = tid & 15;
    if (node >= N_) return;
    const float* hr = g_hfin + (size_t)node * F_;
    float acc = b[o];
#pragma unroll 8
    for (int f = 0; f < F_; f++) acc += hr[f] * sW[f * OUT_ + o];
    out[(size_t)node * OUT_ + o] = acc;
}

// ---------------------------------------------------------------------------
// Host launcher — graph-capturable
// ---------------------------------------------------------------------------
extern "C" void kernel_launch(void* const* d_in, const int* in_sizes, int n_in,
                              void* d_out, int out_size) {
    const float* h = (const float*)d_in[0];
    const int* srcs[4] = {(const int*)d_in[1], (const int*)d_in[3], (const int*)d_in[5], (const int*)d_in[7]};
    const int* dsts[4] = {(const int*)d_in[2], (const int*)d_in[4], (const int*)d_in[6], (const int*)d_in[8]};
    int Eg[4] = {in_sizes[1], in_sizes[3], in_sizes[5], in_sizes[7]};
    const float* fcW = (const float*)d_in[10];
    const float* W[2]    = {(const float*)d_in[11], (const float*)d_in[18]};
    const float* al[2]   = {(const float*)d_in[12], (const float*)d_in[19]};
    const float* ar[2]   = {(const float*)d_in[13], (const float*)d_in[20]};
    const float* bb[2]   = {(const float*)d_in[14], (const float*)d_in[21]};
    const float* saW1[2] = {(const float*)d_in[15], (const float*)d_in[22]};
    const float* sab1[2] = {(const float*)d_in[16], (const float*)d_in[23]};
    const float* saw2[2] = {(const float*)d_in[17], (const float*)d_in[24]};
    const float* saW1f = (const float*)d_in[25];
    const float* sab1f = (const float*)d_in[26];
    const float* saw2f = (const float*)d_in[27];
    const float* predW = (const float*)d_in[28];
    const float* predb = (const float*)d_in[29];
    float* out = (float*)d_out;

    k_fc<<<(N_ + 15) / 16, 256>>>(h, fcW);

    for (int g = 0; g < 4; g++) {
        int E = Eg[g];
        k_zerocnt<<<SCB_N, 256>>>();
        k_hist<<<(E + 255) / 256, 256>>>(dsts[g], E);
        k_scan1<<<SCB_N, 256>>>(g);
        k_scan2<<<1, 256>>>(g);
        k_scan3<<<SCB_N, 256>>>(g);
        k_scatter<<<(E + 255) / 256, 256>>>(srcs[g], dsts[g], E, g);
    }

    const int graphsel[2][3] = {{0, 1, 2}, {0, 1, 3}};
    for (int L = 0; L < 2; L++) {
        for (int m = 0; m < 3; m++) {
            int g = graphsel[L][m];
            k_z<<<(N_ + 63) / 64, 256>>>(W[L] + (size_t)m * HID_ * F_);
            k_eler<<<(N_ + 7) / 8, 256>>>(al[L] + m * F_, ar[L] + m * F_);
            k_conv<<<(N_ + 7) / 8, 256>>>(g, bb[L] + m * F_, m);
        }
        k_prepW1<<<(SAH_ * F_ + 255) / 256, 256>>>(saW1[L]);
        k_wscore_tc<<<dim3(WSB_N, 3), 256>>>(0, sab1[L], saw2[L]);
        k_beta<<<1, 32>>>(3);
        k_combine<<<(int)((NF / 4 + 255) / 256), 256>>>(0, 3, L, nullptr);
    }

    k_prepW1<<<(SAH_ * F_ + 255) / 256, 256>>>(saW1f);
    k_wscore_tc<<<dim3(WSB_N, 2), 256>>>(1, sab1f, saw2f);
    k_beta<<<1, 32>>>(2);
    float* dup = (out_size >= N_ * (OUT_ + F_)) ? out + (size_t)N_ * OUT_ : nullptr;
    k_combine<<<(int)((NF / 4 + 255) / 256), 256>>>(1, 2, 2, dup);

    k_pred<<<(N_ + 15) / 16, 256>>>(predW, predb, out);
}

// round 8
// speedup vs baseline: 4.1214x; 1.0676x over previous
#include <cuda_runtime.h>
#include <math.h>
#include <float.h>

// ---------------------------------------------------------------------------
// Problem constants
// ---------------------------------------------------------------------------
constexpr int N_   = 50000;
constexpr int IN_  = 128;
constexpr int HID_ = 64;
constexpr int H_   = 4;
constexpr int F_   = 256;    // H*D
constexpr int OUT_ = 16;
constexpr int SAH_ = 128;
constexpr int EMAX_ = 800000;

constexpr size_t NF = (size_t)N_ * F_;
constexpr int SC4N = 4 * N_;                   // batched CSR scan length
constexpr int SCB4 = (SC4N + 255) / 256;       // 782 scan blocks
constexpr int WSB_N = (N_ + 127) / 128;        // wscore node-tiles

// ---------------------------------------------------------------------------
// Device scratch (static — no cudaMalloc allowed)
// ---------------------------------------------------------------------------
__device__ float g_x[(size_t)N_ * HID_];
__device__ __align__(16) float g_el[N_ * H_];
__device__ __align__(16) float g_er[N_ * H_];
__device__ __align__(16) float g_wtab[HID_ * 8];   // [k][o]: o<4 = W·al, o>=4 = W·ar
__device__ float g_agg[NF];                        // [n][k][h] head-aggregates in x-space
__device__ float g_emb[6 * NF];                    // [layer*3+m]
__device__ float g_hl[2 * NF];
__device__ float g_hfin[NF];
__device__ float g_wsum[3][4];
__device__ float g_beta[3][4];
__device__ unsigned int g_W1t[SAH_ * F_];          // tf32 bits, [k][f]

// Batched CSR scratch (flat across the 4 graphs)
__device__ int g_cnt4[SC4N];
__device__ int g_cursor4[SC4N];
__device__ int g_prefix[SC4N + 1];
__device__ int g_esrcF[4 * EMAX_];
__device__ int g_bsum[SCB4];
__device__ int g_boff[SCB4];

struct G4 { const int* s[4]; const int* d[4]; int E[4]; };

// ---------------------------------------------------------------------------
// Low-level helpers
// ---------------------------------------------------------------------------
__device__ __forceinline__ unsigned int f2tf32(float f) {
    unsigned int r;
    asm("cvt.rna.tf32.f32 %0, %1;" : "=r"(r) : "f"(f));
    return r;
}
__device__ __forceinline__ float tanh_fast(float x) {
    float r;
    asm("tanh.approx.f32 %0, %1;" : "=f"(r) : "f"(x));
    return r;
}
__device__ __forceinline__ void mma_tf32(float& d0, float& d1, float& d2, float& d3,
                                         unsigned int a0, unsigned int a1,
                                         unsigned int a2, unsigned int a3,
                                         unsigned int b0, unsigned int b1) {
    asm("mma.sync.aligned.m16n8k8.row.col.f32.tf32.tf32.f32 "
        "{%0,%1,%2,%3}, {%4,%5,%6,%7}, {%8,%9}, {%0,%1,%2,%3};"
        : "+f"(d0), "+f"(d1), "+f"(d2), "+f"(d3)
        : "r"(a0), "r"(a1), "r"(a2), "r"(a3), "r"(b0), "r"(b1));
}

// ---------------------------------------------------------------------------
// x = h @ fc_W   [N,128] @ [128,64]
// ---------------------------------------------------------------------------
__global__ void k_fc(const float* __restrict__ h, const float* __restrict__ W) {
    __shared__ __align__(16) float sW[IN_ * HID_];
    __shared__ __align__(16) float sh[16 * IN_];
    int tid = threadIdx.x;
    for (int i = tid; i < IN_ * HID_; i += 256) sW[i] = W[i];
    int row0 = blockIdx.x * 16;
    for (int i = tid; i < 16 * IN_; i += 256) {
        int r = i >> 7, k = i & 127;
        sh[i] = (row0 + r < N_) ? h[(size_t)(row0 + r) * IN_ + k] : 0.f;
    }
    __syncthreads();
    int col = tid & 63;
    for (int rr = tid >> 6; rr < 16; rr += 4) {
        float acc = 0.f;
#pragma unroll
        for (int k = 0; k < IN_; k += 4) {
            float4 hv = *(const float4*)&sh[rr * IN_ + k];
            acc += hv.x * sW[k * HID_ + col] + hv.y * sW[(k + 1) * HID_ + col]
                 + hv.z * sW[(k + 2) * HID_ + col] + hv.w * sW[(k + 3) * HID_ + col];
        }
        if (row0 + rr < N_) g_x[(size_t)(row0 + rr) * HID_ + col] = acc;
    }
}

// ---------------------------------------------------------------------------
// wtab[k][h]   = sum_d W[k,h,d]*al[h,d]   (o = h)
// wtab[k][4+h] = sum_d W[k,h,d]*ar[h,d]
// One block, 256 threads: thread = k*4 + h
// ---------------------------------------------------------------------------
__global__ void k_prew(const float* __restrict__ W, const float* __restrict__ al,
                       const float* __restrict__ ar) {
    int tid = threadIdx.x;
    int k = tid >> 2, h = tid & 3;
    const float* wr = W + k * F_ + h * 64;
    const float* alr = al + h * 64;
    const float* arr = ar + h * 64;
    float a = 0.f, b = 0.f;
#pragma unroll 8
    for (int d = 0; d < 64; d++) { a += wr[d] * alr[d]; b += wr[d] * arr[d]; }
    g_wtab[k * 8 + h] = a;
    g_wtab[k * 8 + 4 + h] = b;
}

// ---------------------------------------------------------------------------
// el/er = x @ wtab   (8 outputs per node).  Block: 32 nodes x 8 outputs.
// ---------------------------------------------------------------------------
__global__ void __launch_bounds__(256) k_eler3() {
    __shared__ float swt[HID_ * 8];
    int tid = threadIdx.x;
    for (int i = tid; i < HID_ * 8; i += 256) swt[i] = g_wtab[i];
    __syncthreads();
    int n = blockIdx.x * 32 + (tid >> 3);
    int o = tid & 7;
    if (n >= N_) return;
    const float4* xr = (const float4*)(g_x + (size_t)n * HID_);
    float acc = 0.f;
#pragma unroll
    for (int q = 0; q < 16; q++) {
        float4 v = xr[q];
        acc += v.x * swt[(q * 4 + 0) * 8 + o] + v.y * swt[(q * 4 + 1) * 8 + o]
             + v.z * swt[(q * 4 + 2) * 8 + o] + v.w * swt[(q * 4 + 3) * 8 + o];
    }
    if (o < 4) g_el[n * 4 + o] = acc;
    else       g_er[n * 4 + (o - 4)] = acc;
}

// ---------------------------------------------------------------------------
// Batched CSR construction over all 4 graphs (flat, absolute offsets)
// ---------------------------------------------------------------------------
__global__ void k_zerocnt4() {
    int i = blockIdx.x * 256 + threadIdx.x;
    if (i < SC4N) g_cnt4[i] = 0;
}
__global__ void k_hist4(G4 a) {
    int g = blockIdx.y;
    int i = blockIdx.x * 256 + threadIdx.x;
    if (i < a.E[g]) atomicAdd(&g_cnt4[g * N_ + a.d[g][i]], 1);
}

template <int NW>
__device__ __forceinline__ int scan_excl(int v, int tid, int* total) {
    int lane = tid & 31, w = tid >> 5;
    int x = v;
#pragma unroll
    for (int o = 1; o < 32; o <<= 1) {
        int y = __shfl_up_sync(0xffffffffu, x, o);
        if (lane >= o) x += y;
    }
    __shared__ int ws[NW];
    if (lane == 31) ws[w] = x;
    __syncthreads();
    if (w == 0) {
        int s = (lane < NW) ? ws[lane] : 0;
#pragma unroll
        for (int o = 1; o < NW; o <<= 1) {
            int y = __shfl_up_sync(0xffffffffu, s, o);
            if (lane >= o) s += y;
        }
        if (lane < NW) ws[lane] = s;
    }
    __syncthreads();
    int base = (w > 0) ? ws[w - 1] : 0;
    *total = ws[NW - 1];
    return base + x - v;
}

__global__ void k_scan1b() {
    int tid = threadIdx.x, b = blockIdx.x;
    int i = b * 256 + tid;
    int v = (i < SC4N) ? g_cnt4[i] : 0;
    int total;
    int excl = scan_excl<8>(v, tid, &total);
    if (i < SC4N) g_prefix[i] = excl;
    if (tid == 0) g_bsum[b] = total;
}
__global__ void k_scan2b() {
    int tid = threadIdx.x;
    int v = (tid < SCB4) ? g_bsum[tid] : 0;
    int total;
    int excl = scan_excl<32>(v, tid, &total);
    if (tid < SCB4) g_boff[tid] = excl;
    if (tid == 0) g_prefix[SC4N] = total;
}
__global__ void k_scan3b() {
    int i = blockIdx.x * 256 + threadIdx.x;
    if (i < SC4N) {
        int r = g_prefix[i] + g_boff[i >> 8];
        g_prefix[i] = r;
        g_cursor4[i] = r;
    }
}
__global__ void k_scatter4(G4 a) {
    int g = blockIdx.y;
    int i = blockIdx.x * 256 + threadIdx.x;
    if (i >= a.E[g]) return;
    int d = a.d[g][i];
    int pos = atomicAdd(&g_cursor4[g * N_ + d], 1);
    g_esrcF[pos] = a.s[g][i];
}

// ---------------------------------------------------------------------------
// x-space gather-accumulate: per edge, per lane float2 of x; 4 head alphas.
// acc layout: acc[h*2+j] for x element k = lane*2+j.
// ---------------------------------------------------------------------------
__device__ __forceinline__ void gather_acc2(const int* __restrict__ ssrc,
                                            const float4* __restrict__ salpha,
                                            int cnt, int lane, float acc[8]) {
    int i = 0;
    for (; i + 4 <= cnt; i += 4) {
        int s0 = ssrc[i], s1 = ssrc[i + 1], s2 = ssrc[i + 2], s3 = ssrc[i + 3];
        float4 a0 = salpha[i], a1 = salpha[i + 1], a2 = salpha[i + 2], a3 = salpha[i + 3];
        float2 x0 = *(const float2*)(g_x + (size_t)s0 * HID_ + lane * 2);
        float2 x1 = *(const float2*)(g_x + (size_t)s1 * HID_ + lane * 2);
        float2 x2 = *(const float2*)(g_x + (size_t)s2 * HID_ + lane * 2);
        float2 x3 = *(const float2*)(g_x + (size_t)s3 * HID_ + lane * 2);
        acc[0] += a0.x * x0.x; acc[1] += a0.x * x0.y;
        acc[2] += a0.y * x0.x; acc[3] += a0.y * x0.y;
        acc[4] += a0.z * x0.x; acc[5] += a0.z * x0.y;
        acc[6] += a0.w * x0.x; acc[7] += a0.w * x0.y;
        acc[0] += a1.x * x1.x; acc[1] += a1.x * x1.y;
        acc[2] += a1.y * x1.x; acc[3] += a1.y * x1.y;
        acc[4] += a1.z * x1.x; acc[5] += a1.z * x1.y;
        acc[6] += a1.w * x1.x; acc[7] += a1.w * x1.y;
        acc[0] += a2.x * x2.x; acc[1] += a2.x * x2.y;
        acc[2] += a2.y * x2.x; acc[3] += a2.y * x2.y;
        acc[4] += a2.z * x2.x; acc[5] += a2.z * x2.y;
        acc[6] += a2.w * x2.x; acc[7] += a2.w * x2.y;
        acc[0] += a3.x * x3.x; acc[1] += a3.x * x3.y;
        acc[2] += a3.y * x3.x; acc[3] += a3.y * x3.y;
        acc[4] += a3.z * x3.x; acc[5] += a3.z * x3.y;
        acc[6] += a3.w * x3.x; acc[7] += a3.w * x3.y;
    }
    for (; i < cnt; i++) {
        int s = ssrc[i];
        float4 a = salpha[i];
        float2 xv = *(const float2*)(g_x + (size_t)s * HID_ + lane * 2);
        acc[0] += a.x * xv.x; acc[1] += a.x * xv.y;
        acc[2] += a.y * xv.x; acc[3] += a.y * xv.y;
        acc[4] += a.z * xv.x; acc[5] += a.z * xv.y;
        acc[6] += a.w * xv.x; acc[7] += a.w * xv.y;
    }
}

// ---------------------------------------------------------------------------
// GAT conv in x-space — WARP per dst node. Writes agg[n][k][h].
// ---------------------------------------------------------------------------
__global__ void __launch_bounds__(256) k_conv2(int gi) {
    __shared__ int s_src[8][32];
    __shared__ __align__(16) float4 s_alpha[8][32];

    int tid = threadIdx.x, lane = tid & 31, w = tid >> 5;
    int n = blockIdx.x * 8 + w;
    if (n >= N_) return;

    int e0 = g_prefix[gi * N_ + n], e1 = g_prefix[gi * N_ + n + 1];
    int deg = e1 - e0;

    float4 ern = *(const float4*)(g_er + n * 4);
    float acc[8] = {0.f, 0.f, 0.f, 0.f, 0.f, 0.f, 0.f, 0.f};

    if (deg > 0 && deg <= 32) {
        int s = -1;
        float v0 = -FLT_MAX, v1 = -FLT_MAX, v2 = -FLT_MAX, v3 = -FLT_MAX;
        if (lane < deg) {
            s = g_esrcF[e0 + lane];
            float4 els = *(const float4*)(g_el + s * 4);
            v0 = els.x + ern.x; v0 = v0 > 0.f ? v0 : 0.2f * v0;
            v1 = els.y + ern.y; v1 = v1 > 0.f ? v1 : 0.2f * v1;
            v2 = els.z + ern.z; v2 = v2 > 0.f ? v2 : 0.2f * v2;
            v3 = els.w + ern.w; v3 = v3 > 0.f ? v3 : 0.2f * v3;
        }
        float m0 = v0, m1 = v1, m2 = v2, m3 = v3;
#pragma unroll
        for (int o = 16; o > 0; o >>= 1) {
            m0 = fmaxf(m0, __shfl_xor_sync(0xffffffffu, m0, o));
            m1 = fmaxf(m1, __shfl_xor_sync(0xffffffffu, m1, o));
            m2 = fmaxf(m2, __shfl_xor_sync(0xffffffffu, m2, o));
            m3 = fmaxf(m3, __shfl_xor_sync(0xffffffffu, m3, o));
        }
        float e0f = (lane < deg) ? __expf(v0 - m0) : 0.f;
        float e1f = (lane < deg) ? __expf(v1 - m1) : 0.f;
        float e2f = (lane < deg) ? __expf(v2 - m2) : 0.f;
        float e3f = (lane < deg) ? __expf(v3 - m3) : 0.f;
        float s0 = e0f, s1 = e1f, s2 = e2f, s3 = e3f;
#pragma unroll
        for (int o = 16; o > 0; o >>= 1) {
            s0 += __shfl_xor_sync(0xffffffffu, s0, o);
            s1 += __shfl_xor_sync(0xffffffffu, s1, o);
            s2 += __shfl_xor_sync(0xffffffffu, s2, o);
            s3 += __shfl_xor_sync(0xffffffffu, s3, o);
        }
        s_src[w][lane] = s;
        s_alpha[w][lane] = make_float4(e0f / s0, e1f / s1, e2f / s2, e3f / s3);
        __syncwarp();
        gather_acc2(s_src[w], s_alpha[w], deg, lane, acc);
    } else if (deg > 32) {
        float mx[4] = {-FLT_MAX, -FLT_MAX, -FLT_MAX, -FLT_MAX};
        float sm[4] = {0.f, 0.f, 0.f, 0.f};
        for (int e = e0 + lane; e < e1; e += 32) {
            int s = g_esrcF[e];
            float4 els = *(const float4*)(g_el + s * 4);
            float v[4];
            v[0] = els.x + ern.x; v[1] = els.y + ern.y;
            v[2] = els.z + ern.z; v[3] = els.w + ern.w;
#pragma unroll
            for (int h = 0; h < 4; h++) {
                float vv = v[h] > 0.f ? v[h] : 0.2f * v[h];
                float nm = fmaxf(mx[h], vv);
                sm[h] = sm[h] * __expf(mx[h] - nm) + __expf(vv - nm);
                mx[h] = nm;
            }
        }
#pragma unroll
        for (int h = 0; h < 4; h++) {
#pragma unroll
            for (int o = 16; o > 0; o >>= 1) {
                float om = __shfl_xor_sync(0xffffffffu, mx[h], o);
                float os = __shfl_xor_sync(0xffffffffu, sm[h], o);
                float nm = fmaxf(mx[h], om);
                sm[h] = sm[h] * __expf(mx[h] - nm) + os * __expf(om - nm);
                mx[h] = nm;
            }
        }
        float inv[4];
#pragma unroll
        for (int h = 0; h < 4; h++) inv[h] = 1.f / sm[h];

        for (int base = 0; base < deg; base += 32) {
            int cnt = min(32, deg - base);
            int s = -1;
            float4 al4 = make_float4(0.f, 0.f, 0.f, 0.f);
            if (lane < cnt) {
                s = g_esrcF[e0 + base + lane];
                float4 els = *(const float4*)(g_el + s * 4);
                float v0 = els.x + ern.x; v0 = v0 > 0.f ? v0 : 0.2f * v0;
                float v1 = els.y + ern.y; v1 = v1 > 0.f ? v1 : 0.2f * v1;
                float v2 = els.z + ern.z; v2 = v2 > 0.f ? v2 : 0.2f * v2;
                float v3 = els.w + ern.w; v3 = v3 > 0.f ? v3 : 0.2f * v3;
                al4 = make_float4(__expf(v0 - mx[0]) * inv[0], __expf(v1 - mx[1]) * inv[1],
                                  __expf(v2 - mx[2]) * inv[2], __expf(v3 - mx[3]) * inv[3]);
            }
            __syncwarp();
            s_src[w][lane] = s;
            s_alpha[w][lane] = al4;
            __syncwarp();
            gather_acc2(s_src[w], s_alpha[w], cnt, lane, acc);
        }
    }

    float4* op = (float4*)(g_agg + (size_t)n * F_ + (lane * 2) * 4);
    op[0] = make_float4(acc[0], acc[2], acc[4], acc[6]);   // k = 2*lane,   h=0..3
    op[1] = make_float4(acc[1], acc[3], acc[5], acc[7]);   // k = 2*lane+1, h=0..3
}

// ---------------------------------------------------------------------------
// Post-GEMM: emb[n,h,d] = elu( sum_k agg[n,h,k] * W[k,h,d] + b[h,d] )
// Block: 32 nodes, 256 threads (thread = h*64+d). Weights in registers.
// ---------------------------------------------------------------------------
__global__ void __launch_bounds__(256) k_post(const float* __restrict__ W,
                                              const float* __restrict__ bias, int slot) {
    __shared__ float sagg[32 * 272];   // [r][h*68 + k], padded: conflict-free
    int tid = threadIdx.x;
    int h = tid >> 6, d = tid & 63;
    float wreg[HID_];
#pragma unroll
    for (int k = 0; k < HID_; k++) wreg[k] = W[k * F_ + h * 64 + d];  // coalesced in tid
    float bv = bias[tid];
    int n0 = blockIdx.x * 32;
    for (int idx = tid; idx < 32 * 256; idx += 256) {
        int r = idx >> 8, j = idx & 255;
        int kk = j >> 2, hh = j & 3;
        float v = (n0 + r < N_) ? g_agg[(size_t)(n0 + r) * F_ + j] : 0.f;
        sagg[r * 272 + hh * 68 + kk] = v;
    }
    __syncthreads();
    int rmax = min(32, N_ - n0);
    for (int r = 0; r < rmax; r++) {
        const float4* ap = (const float4*)(sagg + r * 272 + h * 68);
        float acc = 0.f;
#pragma unroll
        for (int q = 0; q < 16; q++) {
            float4 v = ap[q];
            acc += v.x * wreg[q * 4] + v.y * wreg[q * 4 + 1]
                 + v.z * wreg[q * 4 + 2] + v.w * wreg[q * 4 + 3];
        }
        float o = acc + bv;
        g_emb[(size_t)slot * NF + (size_t)(n0 + r) * F_ + tid] = o > 0.f ? o : expm1f(o);
    }
}

// ---------------------------------------------------------------------------
// W1 prep: transpose + tf32-convert, and zero wsum[stage]
// ---------------------------------------------------------------------------
__global__ void k_prepW1(const float* __restrict__ W1, int stage) {
    int j = blockIdx.x * 256 + threadIdx.x;
    if (j < SAH_ * F_) {
        int k = j >> 8, f = j & 255;
        g_W1t[j] = f2tf32(W1[f * SAH_ + k]);
    }
    if (blockIdx.x == 0 && threadIdx.x < 4) g_wsum[stage][threadIdx.x] = 0.f;
}

// ---------------------------------------------------------------------------
// Semantic-attention score GEMM on tensor cores (tf32 mma.sync).
// ---------------------------------------------------------------------------
__global__ void __launch_bounds__(256) k_wscore_tc(int sel, int layer, int stage,
                                                   const float* __restrict__ b1,
                                                   const float* __restrict__ w2) {
    __shared__ unsigned int sA[128][36];
    __shared__ unsigned int sB[128][36];
    __shared__ float s_b1[SAH_], s_w2[SAH_];
    __shared__ float sred[8];

    int tid = threadIdx.x, lane = tid & 31, w = tid >> 5;
    int m = blockIdx.y;
    int n0 = blockIdx.x * 128;
    const float* Z = sel ? (g_hl + (size_t)m * NF)
                         : (g_emb + (size_t)(layer * 3 + m) * NF);
    if (tid < SAH_) { s_b1[tid] = b1[tid]; s_w2[tid] = w2[tid]; }

    float acc[16][4];
#pragma unroll
    for (int t = 0; t < 16; t++)
#pragma unroll
        for (int j = 0; j < 4; j++) acc[t][j] = 0.f;

    int g4 = lane >> 2, tg = lane & 3;
    int ar0 = w * 16 + g4, ar1 = ar0 + 8;

    for (int f0 = 0; f0 < F_; f0 += 32) {
        __syncthreads();
        for (int i = tid; i < 128 * 8; i += 256) {
            int r = i >> 3, q = i & 7;
            int n = n0 + r;
            float4 v = make_float4(0.f, 0.f, 0.f, 0.f);
            if (n < N_) v = *(const float4*)&Z[(size_t)n * F_ + f0 + q * 4];
            sA[r][q * 4 + 0] = f2tf32(v.x);
            sA[r][q * 4 + 1] = f2tf32(v.y);
            sA[r][q * 4 + 2] = f2tf32(v.z);
            sA[r][q * 4 + 3] = f2tf32(v.w);
        }
        for (int i = tid; i < 128 * 8; i += 256) {
            int k = i >> 3, q = i & 7;
            uint4 v = *(const uint4*)&g_W1t[k * F_ + f0 + q * 4];
            sB[k][q * 4 + 0] = v.x;
            sB[k][q * 4 + 1] = v.y;
            sB[k][q * 4 + 2] = v.z;
            sB[k][q * 4 + 3] = v.w;
        }
        __syncthreads();
#pragma unroll
        for (int kk = 0; kk < 32; kk += 8) {
            unsigned int a0 = sA[ar0][kk + tg];
            unsigned int a1 = sA[ar1][kk + tg];
            unsigned int a2 = sA[ar0][kk + tg + 4];
            unsigned int a3 = sA[ar1][kk + tg + 4];
#pragma unroll
            for (int t = 0; t < 16; t++) {
                int c = t * 8 + g4;
                unsigned int b0v = sB[c][kk + tg];
                unsigned int b1v = sB[c][kk + tg + 4];
                mma_tf32(acc[t][0], acc[t][1], acc[t][2], acc[t][3],
                         a0, a1, a2, a3, b0v, b1v);
            }
        }
    }

    float tot = 0.f;
    bool v0 = (n0 + ar0) < N_, v1 = (n0 + ar1) < N_;
#pragma unroll
    for (int t = 0; t < 16; t++) {
        int c0 = t * 8 + tg * 2, c1 = c0 + 1;
        float bb0 = s_b1[c0], bb1 = s_b1[c1];
        float ww0 = s_w2[c0], ww1 = s_w2[c1];
        if (v0) tot += tanh_fast(acc[t][0] + bb0) * ww0 + tanh_fast(acc[t][1] + bb1) * ww1;
        if (v1) tot += tanh_fast(acc[t][2] + bb0) * ww0 + tanh_fast(acc[t][3] + bb1) * ww1;
    }
#pragma unroll
    for (int o = 16; o > 0; o >>= 1) tot += __shfl_xor_sync(0xffffffffu, tot, o);
    if (lane == 0) sred[w] = tot;
    __syncthreads();
    if (tid == 0) {
        float s = 0.f;
#pragma unroll
        for (int i = 0; i < 8; i++) s += sred[i];
        atomicAdd(&g_wsum[stage][m], s);
    }
}

__global__ void k_beta(int stage, int M) {
    if (threadIdx.x == 0) {
        float w[3];
        float mx = -1e30f;
        for (int m = 0; m < M; m++) { w[m] = g_wsum[stage][m] / (float)N_; mx = fmaxf(mx, w[m]); }
        float s = 0.f;
        for (int m = 0; m < M; m++) { w[m] = __expf(w[m] - mx); s += w[m]; }
        for (int m = 0; m < M; m++) g_beta[stage][m] = w[m] / s;
    }
}

// stage 0/1: base emb[stage*3..], M=3, out hl[stage]; stage 2: base hl, M=2, out hfin (+dup)
__global__ void k_combine(int stage, float* __restrict__ dup) {
    size_t i = ((size_t)blockIdx.x * 256 + threadIdx.x) * 4;
    if (i >= NF) return;
    const float* base = (stage < 2) ? (g_emb + (size_t)stage * 3 * NF) : g_hl;
    float b0 = g_beta[stage][0], b1 = g_beta[stage][1], b2 = g_beta[stage][2];
    float4 v0 = *(const float4*)&base[i];
    float4 v1 = *(const float4*)&base[NF + i];
    float4 r;
    r.x = b0 * v0.x + b1 * v1.x;
    r.y = b0 * v0.y + b1 * v1.y;
    r.z = b0 * v0.z + b1 * v1.z;
    r.w = b0 * v0.w + b1 * v1.w;
    if (stage < 2) {
        float4 v2 = *(const float4*)&base[2 * NF + i];
        r.x += b2 * v2.x; r.y += b2 * v2.y; r.z += b2 * v2.z; r.w += b2 * v2.w;
    }
    float* out = (stage == 0) ? g_hl : (stage == 1 ? g_hl + NF : g_hfin);
    *(float4*)&out[i] = r;
    if (dup) *(float4*)&dup[i] = r;
}

// ---------------------------------------------------------------------------
// logits = h_final @ pred_W + pred_b
// ---------------------------------------------------------------------------
__global__ void k_pred(const float* __restrict__ W, const float* __restrict__ b,
                       float* __restrict__ out) {
    __shared__ float sW[F_ * OUT_];
    int tid = threadIdx.x;
    for (int i = tid; i < F_ * OUT_; i += 256) sW[i] = W[i];
    __syncthreads();
    int node = blockIdx.x * 16 + (tid >> 4);
    int o = tid & 15;
    if (node >= N_) return;
    const float* hr = g_hfin + (size_t)node * F_;
    float acc = b[o];
#pragma unroll 8
    for (int f = 0; f < F_; f++) acc += hr[f] * sW[f * OUT_ + o];
    out[(size_t)node * OUT_ + o] = acc;
}

// ---------------------------------------------------------------------------
// Host launcher — single stream, graph-capturable, no persistent objects
// ---------------------------------------------------------------------------
extern "C" void kernel_launch(void* const* d_in, const int* in_sizes, int n_in,
                              void* d_out, int out_size) {
    const float* h = (const float*)d_in[0];
    G4 a;
    a.s[0] = (const int*)d_in[1]; a.d[0] = (const int*)d_in[2];
    a.s[1] = (const int*)d_in[3]; a.d[1] = (const int*)d_in[4];
    a.s[2] = (const int*)d_in[5]; a.d[2] = (const int*)d_in[6];
    a.s[3] = (const int*)d_in[7]; a.d[3] = (const int*)d_in[8];
    a.E[0] = in_sizes[1]; a.E[1] = in_sizes[3]; a.E[2] = in_sizes[5]; a.E[3] = in_sizes[7];
    const float* fcW = (const float*)d_in[10];
    const float* W[2]    = {(const float*)d_in[11], (const float*)d_in[18]};
    const float* al[2]   = {(const float*)d_in[12], (const float*)d_in[19]};
    const float* ar[2]   = {(const float*)d_in[13], (const float*)d_in[20]};
    const float* bb[2]   = {(const float*)d_in[14], (const float*)d_in[21]};
    const float* saW1[2] = {(const float*)d_in[15], (const float*)d_in[22]};
    const float* sab1[2] = {(const float*)d_in[16], (const float*)d_in[23]};
    const float* saw2[2] = {(const float*)d_in[17], (const float*)d_in[24]};
    const float* saW1f = (const float*)d_in[25];
    const float* sab1f = (const float*)d_in[26];
    const float* saw2f = (const float*)d_in[27];
    const float* predW = (const float*)d_in[28];
    const float* predb = (const float*)d_in[29];
    float* out = (float*)d_out;

    const int graphsel[2][3] = {{0, 1, 2}, {0, 1, 3}};
    const int Wtile = HID_ * F_;
    int maxE = a.E[0];
    for (int g = 1; g < 4; g++) if (a.E[g] > maxE) maxE = a.E[g];
    const int CMB = (int)((NF / 4 + 255) / 256);

    k_fc<<<(N_ + 15) / 16, 256>>>(h, fcW);

    // Batched CSR (all 4 graphs in one chain)
    k_zerocnt4<<<SCB4, 256>>>();
    k_hist4<<<dim3((maxE + 255) / 256, 4), 256>>>(a);
    k_scan1b<<<SCB4, 256>>>();
    k_scan2b<<<1, 1024>>>();
    k_scan3b<<<SCB4, 256>>>();
    k_scatter4<<<dim3((maxE + 255) / 256, 4), 256>>>(a);

    for (int L = 0; L < 2; L++) {
        for (int m = 0; m < 3; m++) {
            int g = graphsel[L][m];
            int slot = L * 3 + m;
            const float* Wm = W[L] + (size_t)m * Wtile;
            k_prew<<<1, 256>>>(Wm, al[L] + m * F_, ar[L] + m * F_);
            k_eler3<<<(N_ + 31) / 32, 256>>>();
            k_conv2<<<(N_ + 7) / 8, 256>>>(g);
            k_post<<<(N_ + 31) / 32, 256>>>(Wm, bb[L] + m * F_, slot);
        }
        k_prepW1<<<(SAH_ * F_ + 255) / 256, 256>>>(saW1[L], L);
        k_wscore_tc<<<dim3(WSB_N, 3), 256>>>(0, L, L, sab1[L], saw2[L]);
        k_beta<<<1, 32>>>(L, 3);
        k_combine<<<CMB, 256>>>(L, nullptr);
    }

    k_prepW1<<<(SAH_ * F_ + 255) / 256, 256>>>(saW1f, 2);
    k_wscore_tc<<<dim3(WSB_N, 2), 256>>>(1, 0, 2, sab1f, saw2f);
    k_beta<<<1, 32>>>(2, 2);
    float* dup = (out_size >= N_ * (OUT_ + F_)) ? out + (size_t)N_ * OUT_ : nullptr;
    k_combine<<<CMB, 256>>>(2, dup);

    k_pred<<<(N_ + 15) / 16, 256>>>(predW, predb, out);
}